// round 1
// baseline (speedup 1.0000x reference)
#include <cuda_runtime.h>
#include <math.h>

#define DIM   4096
#define NH    32
#define HD    128
#define BSZ   2
#define SEQ   2048
#define NTOK  (BSZ*SEQ)          // 4096 tokens

// ---------------- scratch (allocation-free: __device__ globals) -------------
__device__ float g_q[(size_t)NTOK * DIM];    // rotated Q, 64 MB
__device__ float g_att[(size_t)NTOK * DIM];  // attention output, 64 MB

// ============================================================================
// GEMM (NT): C[m,n] = sum_k A[m,k] * B[n,k];  M=N=K=4096
// 128x128 block tile, BK=8, 256 threads, 8x8 per-thread (split-N 4+4)
// ============================================================================
#define BM 128
#define BN 128
#define BKK 8

__global__ __launch_bounds__(256, 2) void sgemm_nt(const float* __restrict__ A,
                                                   const float* __restrict__ B,
                                                   float* __restrict__ C) {
    __shared__ float As[BKK][BM + 4];
    __shared__ float Bs[BKK][BN + 4];
    const int K = DIM, N = DIM;
    const int t  = threadIdx.x;
    const int bx = blockIdx.x, by = blockIdx.y;

    const int arow = t >> 1;          // 0..127
    const int acol = (t & 1) * 4;     // 0 or 4
    const float* Ag = A + (size_t)(by * BM + arow) * K + acol;
    const float* Bg = B + (size_t)(bx * BN + arow) * K + acol;

    const int r  = t >> 4;            // 0..15 : rows r*8..r*8+7
    const int c  = t & 15;            // 0..15 : cols c*4..+3 and 64+c*4..+3
    const int n0 = c * 4;

    float acc[8][8];
#pragma unroll
    for (int i = 0; i < 8; i++)
#pragma unroll
        for (int j = 0; j < 8; j++) acc[i][j] = 0.f;

    for (int k0 = 0; k0 < K; k0 += BKK) {
        float4 av = *(const float4*)(Ag + k0);
        float4 bv = *(const float4*)(Bg + k0);
        As[acol + 0][arow] = av.x;  As[acol + 1][arow] = av.y;
        As[acol + 2][arow] = av.z;  As[acol + 3][arow] = av.w;
        Bs[acol + 0][arow] = bv.x;  Bs[acol + 1][arow] = bv.y;
        Bs[acol + 2][arow] = bv.z;  Bs[acol + 3][arow] = bv.w;
        __syncthreads();
#pragma unroll
        for (int kk = 0; kk < BKK; kk++) {
            float4 a0 = *(const float4*)&As[kk][r * 8];
            float4 a1 = *(const float4*)&As[kk][r * 8 + 4];
            float4 b0 = *(const float4*)&Bs[kk][n0];
            float4 b1 = *(const float4*)&Bs[kk][n0 + 64];
            float a[8] = {a0.x, a0.y, a0.z, a0.w, a1.x, a1.y, a1.z, a1.w};
            float b[8] = {b0.x, b0.y, b0.z, b0.w, b1.x, b1.y, b1.z, b1.w};
#pragma unroll
            for (int i = 0; i < 8; i++)
#pragma unroll
                for (int j = 0; j < 8; j++)
                    acc[i][j] = fmaf(a[i], b[j], acc[i][j]);
        }
        __syncthreads();
    }

#pragma unroll
    for (int i = 0; i < 8; i++) {
        float* Crow = C + (size_t)(by * BM + r * 8 + i) * N + bx * BN;
        float4 s0 = {acc[i][0], acc[i][1], acc[i][2], acc[i][3]};
        float4 s1 = {acc[i][4], acc[i][5], acc[i][6], acc[i][7]};
        *(float4*)(Crow + n0)      = s0;
        *(float4*)(Crow + n0 + 64) = s1;
    }
}

// ============================================================================
// RoPE: rotate pairs in q (g_q) and k (cache_k region of d_out) in place.
// ============================================================================
__global__ void rope_kernel(float* __restrict__ q, float* __restrict__ k,
                            const float* __restrict__ cs, const float* __restrict__ sn) {
    int idx = blockIdx.x * blockDim.x + threadIdx.x;     // 2^23 total
    int i = idx & 63;
    int s = (idx >> 11) & 2047;
    float cv = cs[s * 64 + i];
    float sv = sn[s * 64 + i];
    size_t base = (size_t)(idx >> 6) * HD + 2 * i;       // (idx>>6) = token*NH+h ordering matches layout
    // careful: idx>>6 enumerates (b,s,h); layout is ((b*SEQ+s)*NH+h). Recompute:
    int h = (idx >> 6) & 31;
    int b = idx >> 22;
    base = ((size_t)((b * SEQ + s) * NH) + h) * HD + 2 * i;
    float2 qv = *(float2*)(q + base);
    float2 kv = *(float2*)(k + base);
    float2 qo, ko;
    qo.x = qv.x * cv - qv.y * sv;  qo.y = qv.x * sv + qv.y * cv;
    ko.x = kv.x * cv - kv.y * sv;  ko.y = kv.x * sv + kv.y * cv;
    *(float2*)(q + base) = qo;
    *(float2*)(k + base) = ko;
}

// ============================================================================
// Flash attention (fp32 SIMT): BQ=BK=32, 256 threads, online softmax.
// Layouts: Q/K/V/O all [B, S, NH, HD].
// ============================================================================
#define BQ 32
#define BKT 32
#define QSS 132
#define KSS 132
#define VSS 128
#define PSS 33

__global__ __launch_bounds__(256) void flash_attn(const float* __restrict__ Q,
                                                  const float* __restrict__ Kc,
                                                  const float* __restrict__ Vc,
                                                  float* __restrict__ O) {
    extern __shared__ float sm[];
    float* Qs = sm;                        // 32*132
    float* Ks = Qs + BQ * QSS;             // 32*132
    float* Vs = Ks + BKT * KSS;            // 32*128
    float* Ps = Vs + BKT * VSS;            // 32*33

    const int t  = threadIdx.x;
    const int qb = blockIdx.x, h = blockIdx.y, b = blockIdx.z;

    // load Q tile
    for (int i = t; i < BQ * HD / 4; i += 256) {
        int rr = i >> 5, c4 = i & 31;
        size_t g = ((size_t)((b * SEQ + qb * BQ + rr) * NH + h)) * HD + c4 * 4;
        *(float4*)(Qs + rr * QSS + c4 * 4) = *(const float4*)(Q + g);
    }

    const int r  = t >> 3;   // q-row within tile
    const int lg = t & 7;    // lane in 8-group; owns k rows lg+8j, d chunks 4lg+32i
    const float scale = 0.08838834764831845f;   // 1/sqrt(128)

    float m_i = -INFINITY, l_i = 0.f;
    float4 o0 = {0,0,0,0}, o1 = o0, o2 = o0, o3 = o0;
    __syncthreads();

    const int qg = qb * BQ + r;
    for (int kb = 0; kb <= qb; kb++) {
        for (int i = t; i < BKT * HD / 4; i += 256) {
            int rr = i >> 5, c4 = i & 31;
            size_t g = ((size_t)((b * SEQ + kb * BKT + rr) * NH + h)) * HD + c4 * 4;
            *(float4*)(Ks + rr * KSS + c4 * 4) = *(const float4*)(Kc + g);
            *(float4*)(Vs + rr * VSS + c4 * 4) = *(const float4*)(Vc + g);
        }
        __syncthreads();

        float s0 = 0.f, s1 = 0.f, s2 = 0.f, s3 = 0.f;
#pragma unroll 8
        for (int d4 = 0; d4 < 32; d4++) {
            float4 qv = *(const float4*)(Qs + r * QSS + d4 * 4);
            float4 k0 = *(const float4*)(Ks + (lg     ) * KSS + d4 * 4);
            float4 k1 = *(const float4*)(Ks + (lg +  8) * KSS + d4 * 4);
            float4 k2 = *(const float4*)(Ks + (lg + 16) * KSS + d4 * 4);
            float4 k3 = *(const float4*)(Ks + (lg + 24) * KSS + d4 * 4);
            s0 += qv.x*k0.x + qv.y*k0.y + qv.z*k0.z + qv.w*k0.w;
            s1 += qv.x*k1.x + qv.y*k1.y + qv.z*k1.z + qv.w*k1.w;
            s2 += qv.x*k2.x + qv.y*k2.y + qv.z*k2.z + qv.w*k2.w;
            s3 += qv.x*k3.x + qv.y*k3.y + qv.z*k3.z + qv.w*k3.w;
        }
        int kbase = kb * BKT;
        s0 = (kbase + lg      <= qg) ? s0 * scale : -1e30f;
        s1 = (kbase + lg +  8 <= qg) ? s1 * scale : -1e30f;
        s2 = (kbase + lg + 16 <= qg) ? s2 * scale : -1e30f;
        s3 = (kbase + lg + 24 <= qg) ? s3 * scale : -1e30f;

        float mx = fmaxf(fmaxf(s0, s1), fmaxf(s2, s3));
        mx = fmaxf(mx, __shfl_xor_sync(0xffffffffu, mx, 1, 8));
        mx = fmaxf(mx, __shfl_xor_sync(0xffffffffu, mx, 2, 8));
        mx = fmaxf(mx, __shfl_xor_sync(0xffffffffu, mx, 4, 8));
        float m_new = fmaxf(m_i, mx);
        float p0 = __expf(s0 - m_new), p1 = __expf(s1 - m_new);
        float p2 = __expf(s2 - m_new), p3 = __expf(s3 - m_new);
        float ps = p0 + p1 + p2 + p3;
        ps += __shfl_xor_sync(0xffffffffu, ps, 1, 8);
        ps += __shfl_xor_sync(0xffffffffu, ps, 2, 8);
        ps += __shfl_xor_sync(0xffffffffu, ps, 4, 8);
        float alpha = __expf(m_i - m_new);
        l_i = l_i * alpha + ps;
        m_i = m_new;
        o0.x *= alpha; o0.y *= alpha; o0.z *= alpha; o0.w *= alpha;
        o1.x *= alpha; o1.y *= alpha; o1.z *= alpha; o1.w *= alpha;
        o2.x *= alpha; o2.y *= alpha; o2.z *= alpha; o2.w *= alpha;
        o3.x *= alpha; o3.y *= alpha; o3.z *= alpha; o3.w *= alpha;

        Ps[r * PSS + lg]      = p0;
        Ps[r * PSS + lg +  8] = p1;
        Ps[r * PSS + lg + 16] = p2;
        Ps[r * PSS + lg + 24] = p3;
        __syncwarp();

#pragma unroll 8
        for (int kk = 0; kk < 32; kk++) {
            float pv = Ps[r * PSS + kk];
            const float4* vrow = (const float4*)(Vs + kk * VSS);
            float4 v0 = vrow[lg], v1 = vrow[lg + 8], v2 = vrow[lg + 16], v3 = vrow[lg + 24];
            o0.x += pv*v0.x; o0.y += pv*v0.y; o0.z += pv*v0.z; o0.w += pv*v0.w;
            o1.x += pv*v1.x; o1.y += pv*v1.y; o1.z += pv*v1.z; o1.w += pv*v1.w;
            o2.x += pv*v2.x; o2.y += pv*v2.y; o2.z += pv*v2.z; o2.w += pv*v2.w;
            o3.x += pv*v3.x; o3.y += pv*v3.y; o3.z += pv*v3.z; o3.w += pv*v3.w;
        }
        __syncthreads();
    }

    float inv = 1.f / l_i;
    o0.x *= inv; o0.y *= inv; o0.z *= inv; o0.w *= inv;
    o1.x *= inv; o1.y *= inv; o1.z *= inv; o1.w *= inv;
    o2.x *= inv; o2.y *= inv; o2.z *= inv; o2.w *= inv;
    o3.x *= inv; o3.y *= inv; o3.z *= inv; o3.w *= inv;
    float* Op = O + ((size_t)((b * SEQ + qg) * NH + h)) * HD;
    *(float4*)(Op + 4 * lg)      = o0;
    *(float4*)(Op + 4 * lg + 32) = o1;
    *(float4*)(Op + 4 * lg + 64) = o2;
    *(float4*)(Op + 4 * lg + 96) = o3;
}

// ============================================================================
// launch
// ============================================================================
extern "C" void kernel_launch(void* const* d_in, const int* in_sizes, int n_in,
                              void* d_out, int out_size) {
    const float* x    = (const float*)d_in[0];
    const float* fcos = (const float*)d_in[1];
    const float* fsin = (const float*)d_in[2];
    // d_in[3] mask, d_in[4] input_idexes, d_in[5] cache_k, d_in[6] cache_v: unused
    const float* wq = (const float*)d_in[7];
    const float* wk = (const float*)d_in[8];
    const float* wv = (const float*)d_in[9];
    const float* wo = (const float*)d_in[10];

    float* out     = (float*)d_out;                               // [B,S,DIM]
    float* cache_k = (float*)d_out + (size_t)NTOK * DIM;          // [B,S,NH,HD]
    float* cache_v = (float*)d_out + (size_t)2 * NTOK * DIM;      // [B,S,NH,HD]

    float* qbuf; cudaGetSymbolAddress((void**)&qbuf, g_q);
    float* abuf; cudaGetSymbolAddress((void**)&abuf, g_att);

    static const int smem_fa = (BQ*QSS + BKT*KSS + BKT*VSS + BQ*PSS) * 4;
    cudaFuncSetAttribute(flash_attn, cudaFuncAttributeMaxDynamicSharedMemorySize, smem_fa);

    dim3 gg(DIM / BN, NTOK / BM);
    sgemm_nt<<<gg, 256>>>(x, wq, qbuf);
    sgemm_nt<<<gg, 256>>>(x, wk, cache_k);
    sgemm_nt<<<gg, 256>>>(x, wv, cache_v);

    rope_kernel<<<(NTOK * NH * 64) / 256, 256>>>(qbuf, cache_k, fcos, fsin);

    dim3 fg(SEQ / BQ, NH, BSZ);
    flash_attn<<<fg, 256, smem_fa>>>(qbuf, cache_k, cache_v, abuf);

    sgemm_nt<<<gg, 256>>>(abuf, wo, out);
}

// round 3
// speedup vs baseline: 1.7945x; 1.7945x over previous
#include <cuda_runtime.h>
#include <math.h>
#include <stdint.h>

#define DIM   4096
#define NH    32
#define HD    128
#define BSZ   2
#define SEQ   2048
#define NTOK  (BSZ*SEQ)          // 4096 tokens

// ---------------- scratch (allocation-free: __device__ globals) -------------
__device__ float g_q[(size_t)NTOK * DIM];    // rotated Q, 64 MB
__device__ float g_att[(size_t)NTOK * DIM];  // attention output, 64 MB

// ============================================================================
// helpers
// ============================================================================
__device__ __forceinline__ uint32_t smem_u32(const void* p) {
    uint32_t a;
    asm("{ .reg .u64 t; cvta.to.shared.u64 t, %1; cvt.u32.u64 %0, t; }"
        : "=r"(a) : "l"(p));
    return a;
}

__device__ __forceinline__ void cp16(uint32_t dst, const void* src) {
    asm volatile("cp.async.cg.shared.global [%0], [%1], 16;" :: "r"(dst), "l"(src));
}
#define CP_COMMIT() asm volatile("cp.async.commit_group;" ::: "memory")
#define CP_WAIT0()  asm volatile("cp.async.wait_group 0;"  ::: "memory")

__device__ __forceinline__ uint32_t f2tf(float f) {
    uint32_t r;
    asm("cvt.rna.tf32.f32 %0, %1;" : "=r"(r) : "f"(f));
    return r;
}

__device__ __forceinline__ void mma16n8k8(float* c, const uint32_t* a, const uint32_t* b) {
    asm volatile(
        "mma.sync.aligned.m16n8k8.row.col.f32.tf32.tf32.f32 "
        "{%0,%1,%2,%3}, {%4,%5,%6,%7}, {%8,%9}, {%0,%1,%2,%3};"
        : "+f"(c[0]), "+f"(c[1]), "+f"(c[2]), "+f"(c[3])
        : "r"(a[0]), "r"(a[1]), "r"(a[2]), "r"(a[3]), "r"(b[0]), "r"(b[1]));
}

// ============================================================================
// tf32 mma.sync GEMM (NT): C[m,n] = sum_k A[m,k]*B[n,k];  M=N=K=4096
// CTA 128x128, 8 warps (2x4), warp tile 64x32, BK=16, cp.async double buffer.
// smem tiles stored [row][k] with stride 20 floats (conflict-free frag loads).
// ============================================================================
#define TS 20                    // smem row stride (floats)
#define NKI (DIM / 16)           // 256 k-iterations

__global__ __launch_bounds__(256, 2) void gemm_mma(const float* __restrict__ A,
                                                   const float* __restrict__ B,
                                                   float* __restrict__ C) {
    __shared__ float As[2][128 * TS];
    __shared__ float Bs[2][128 * TS];

    const int t    = threadIdx.x;
    const int lane = t & 31;
    const int w    = t >> 5;
    const int wm   = w >> 2;          // 0..1
    const int wn   = w & 3;           // 0..3
    const int g    = lane >> 2;       // 0..7
    const int q    = lane & 3;        // 0..3
    const int bm   = blockIdx.y, bn = blockIdx.x;

    const int lrow = t >> 1;          // 0..127  (2 threads per row)
    const int lc   = (t & 1) * 2;     // float4 slot 0 or 2 (each thread does slots lc, lc+1)
    const float* Agp = A + (size_t)(bm * 128 + lrow) * DIM;
    const float* Bgp = B + (size_t)(bn * 128 + lrow) * DIM;
    const uint32_t sA = smem_u32(As), sB = smem_u32(Bs);
    const uint32_t dstA = sA + (lrow * TS) * 4;
    const uint32_t dstB = sB + (lrow * TS) * 4;

    float acc[4][4][4];
#pragma unroll
    for (int i = 0; i < 4; i++)
#pragma unroll
        for (int j = 0; j < 4; j++)
#pragma unroll
            for (int v = 0; v < 4; v++) acc[i][j][v] = 0.f;

    // prefetch k-tile 0 into buffer 0
    {
        cp16(dstA + (lc * 4) * 4,       Agp + lc * 4);
        cp16(dstA + ((lc + 1) * 4) * 4, Agp + (lc + 1) * 4);
        cp16(dstB + (lc * 4) * 4,       Bgp + lc * 4);
        cp16(dstB + ((lc + 1) * 4) * 4, Bgp + (lc + 1) * 4);
        CP_COMMIT();
    }

    for (int i = 0; i < NKI; i++) {
        const int buf = i & 1;
        CP_WAIT0();
        __syncthreads();

        if (i + 1 < NKI) {
            const int nb = buf ^ 1;
            const int k0 = (i + 1) * 16;
            const uint32_t oA = dstA + nb * (128 * TS * 4);
            const uint32_t oB = dstB + nb * (128 * TS * 4);
            cp16(oA + (lc * 4) * 4,       Agp + k0 + lc * 4);
            cp16(oA + ((lc + 1) * 4) * 4, Agp + k0 + (lc + 1) * 4);
            cp16(oB + (lc * 4) * 4,       Bgp + k0 + lc * 4);
            cp16(oB + ((lc + 1) * 4) * 4, Bgp + k0 + (lc + 1) * 4);
            CP_COMMIT();
        }

        const float* Ab = As[buf];
        const float* Bb = Bs[buf];
#pragma unroll
        for (int k8 = 0; k8 < 2; k8++) {
            const int kc = k8 * 8 + q;
            uint32_t af[4][4], bf[4][2];
#pragma unroll
            for (int mt = 0; mt < 4; mt++) {
                const int r0 = wm * 64 + mt * 16 + g;
                af[mt][0] = f2tf(Ab[r0 * TS + kc]);
                af[mt][1] = f2tf(Ab[(r0 + 8) * TS + kc]);
                af[mt][2] = f2tf(Ab[r0 * TS + kc + 4]);
                af[mt][3] = f2tf(Ab[(r0 + 8) * TS + kc + 4]);
            }
#pragma unroll
            for (int nt = 0; nt < 4; nt++) {
                const int c0 = wn * 32 + nt * 8 + g;
                bf[nt][0] = f2tf(Bb[c0 * TS + kc]);
                bf[nt][1] = f2tf(Bb[c0 * TS + kc + 4]);
            }
#pragma unroll
            for (int mt = 0; mt < 4; mt++)
#pragma unroll
                for (int nt = 0; nt < 4; nt++)
                    mma16n8k8(acc[mt][nt], af[mt], bf[nt]);
        }
        __syncthreads();
    }

    // epilogue
#pragma unroll
    for (int mt = 0; mt < 4; mt++) {
        const int row = bm * 128 + wm * 64 + mt * 16 + g;
#pragma unroll
        for (int nt = 0; nt < 4; nt++) {
            const int col = bn * 128 + wn * 32 + nt * 8 + q * 2;
            float2 v0 = {acc[mt][nt][0], acc[mt][nt][1]};
            float2 v1 = {acc[mt][nt][2], acc[mt][nt][3]};
            *(float2*)(C + (size_t)row * DIM + col)       = v0;
            *(float2*)(C + (size_t)(row + 8) * DIM + col) = v1;
        }
    }
}

// ============================================================================
// RoPE: rotate pairs in q (g_q) and k (cache_k region of d_out) in place.
// ============================================================================
__global__ void rope_kernel(float* __restrict__ q, float* __restrict__ k,
                            const float* __restrict__ cs, const float* __restrict__ sn) {
    int idx = blockIdx.x * blockDim.x + threadIdx.x;
    int i = idx & 63;
    int s = (idx >> 11) & 2047;
    float cv = cs[s * 64 + i];
    float sv = sn[s * 64 + i];
    int h = (idx >> 6) & 31;
    int b = idx >> 22;
    size_t base = ((size_t)((b * SEQ + s) * NH) + h) * HD + 2 * i;
    float2 qv = *(float2*)(q + base);
    float2 kv = *(float2*)(k + base);
    float2 qo, ko;
    qo.x = qv.x * cv - qv.y * sv;  qo.y = qv.x * sv + qv.y * cv;
    ko.x = kv.x * cv - kv.y * sv;  ko.y = kv.x * sv + kv.y * cv;
    *(float2*)(q + base) = qo;
    *(float2*)(k + base) = ko;
}

// ============================================================================
// Flash attention (fp32 SIMT): BQ=BK=32, 256 threads, online softmax.
// Layouts: Q/K/V/O all [B, S, NH, HD].
// ============================================================================
#define BQ 32
#define BKT 32
#define QSS 132
#define KSS 132
#define VSS 128
#define PSS 33
#define FA_SMEM ((BQ*QSS + BKT*KSS + BKT*VSS + BQ*PSS) * 4)

__global__ __launch_bounds__(256) void flash_attn(const float* __restrict__ Q,
                                                  const float* __restrict__ Kc,
                                                  const float* __restrict__ Vc,
                                                  float* __restrict__ O) {
    extern __shared__ float sm[];
    float* Qs = sm;                        // 32*132
    float* Ks = Qs + BQ * QSS;             // 32*132
    float* Vs = Ks + BKT * KSS;            // 32*128
    float* Ps = Vs + BKT * VSS;            // 32*33

    const int t  = threadIdx.x;
    const int qb = blockIdx.x, h = blockIdx.y, b = blockIdx.z;

    for (int i = t; i < BQ * HD / 4; i += 256) {
        int rr = i >> 5, c4 = i & 31;
        size_t g = ((size_t)((b * SEQ + qb * BQ + rr) * NH + h)) * HD + c4 * 4;
        *(float4*)(Qs + rr * QSS + c4 * 4) = *(const float4*)(Q + g);
    }

    const int r  = t >> 3;
    const int lg = t & 7;
    const float scale = 0.08838834764831845f;   // 1/sqrt(128)

    float m_i = -INFINITY, l_i = 0.f;
    float4 o0 = {0,0,0,0}, o1 = o0, o2 = o0, o3 = o0;
    __syncthreads();

    const int qg = qb * BQ + r;
    for (int kb = 0; kb <= qb; kb++) {
        for (int i = t; i < BKT * HD / 4; i += 256) {
            int rr = i >> 5, c4 = i & 31;
            size_t g = ((size_t)((b * SEQ + kb * BKT + rr) * NH + h)) * HD + c4 * 4;
            *(float4*)(Ks + rr * KSS + c4 * 4) = *(const float4*)(Kc + g);
            *(float4*)(Vs + rr * VSS + c4 * 4) = *(const float4*)(Vc + g);
        }
        __syncthreads();

        float s0 = 0.f, s1 = 0.f, s2 = 0.f, s3 = 0.f;
#pragma unroll 8
        for (int d4 = 0; d4 < 32; d4++) {
            float4 qv = *(const float4*)(Qs + r * QSS + d4 * 4);
            float4 k0 = *(const float4*)(Ks + (lg     ) * KSS + d4 * 4);
            float4 k1 = *(const float4*)(Ks + (lg +  8) * KSS + d4 * 4);
            float4 k2 = *(const float4*)(Ks + (lg + 16) * KSS + d4 * 4);
            float4 k3 = *(const float4*)(Ks + (lg + 24) * KSS + d4 * 4);
            s0 += qv.x*k0.x + qv.y*k0.y + qv.z*k0.z + qv.w*k0.w;
            s1 += qv.x*k1.x + qv.y*k1.y + qv.z*k1.z + qv.w*k1.w;
            s2 += qv.x*k2.x + qv.y*k2.y + qv.z*k2.z + qv.w*k2.w;
            s3 += qv.x*k3.x + qv.y*k3.y + qv.z*k3.z + qv.w*k3.w;
        }
        int kbase = kb * BKT;
        s0 = (kbase + lg      <= qg) ? s0 * scale : -1e30f;
        s1 = (kbase + lg +  8 <= qg) ? s1 * scale : -1e30f;
        s2 = (kbase + lg + 16 <= qg) ? s2 * scale : -1e30f;
        s3 = (kbase + lg + 24 <= qg) ? s3 * scale : -1e30f;

        float mx = fmaxf(fmaxf(s0, s1), fmaxf(s2, s3));
        mx = fmaxf(mx, __shfl_xor_sync(0xffffffffu, mx, 1, 8));
        mx = fmaxf(mx, __shfl_xor_sync(0xffffffffu, mx, 2, 8));
        mx = fmaxf(mx, __shfl_xor_sync(0xffffffffu, mx, 4, 8));
        float m_new = fmaxf(m_i, mx);
        float p0 = __expf(s0 - m_new), p1 = __expf(s1 - m_new);
        float p2 = __expf(s2 - m_new), p3 = __expf(s3 - m_new);
        float ps = p0 + p1 + p2 + p3;
        ps += __shfl_xor_sync(0xffffffffu, ps, 1, 8);
        ps += __shfl_xor_sync(0xffffffffu, ps, 2, 8);
        ps += __shfl_xor_sync(0xffffffffu, ps, 4, 8);
        float alpha = __expf(m_i - m_new);
        l_i = l_i * alpha + ps;
        m_i = m_new;
        o0.x *= alpha; o0.y *= alpha; o0.z *= alpha; o0.w *= alpha;
        o1.x *= alpha; o1.y *= alpha; o1.z *= alpha; o1.w *= alpha;
        o2.x *= alpha; o2.y *= alpha; o2.z *= alpha; o2.w *= alpha;
        o3.x *= alpha; o3.y *= alpha; o3.z *= alpha; o3.w *= alpha;

        Ps[r * PSS + lg]      = p0;
        Ps[r * PSS + lg +  8] = p1;
        Ps[r * PSS + lg + 16] = p2;
        Ps[r * PSS + lg + 24] = p3;
        __syncwarp();

#pragma unroll 8
        for (int kk = 0; kk < 32; kk++) {
            float pv = Ps[r * PSS + kk];
            const float4* vrow = (const float4*)(Vs + kk * VSS);
            float4 v0 = vrow[lg], v1 = vrow[lg + 8], v2 = vrow[lg + 16], v3 = vrow[lg + 24];
            o0.x += pv*v0.x; o0.y += pv*v0.y; o0.z += pv*v0.z; o0.w += pv*v0.w;
            o1.x += pv*v1.x; o1.y += pv*v1.y; o1.z += pv*v1.z; o1.w += pv*v1.w;
            o2.x += pv*v2.x; o2.y += pv*v2.y; o2.z += pv*v2.z; o2.w += pv*v2.w;
            o3.x += pv*v3.x; o3.y += pv*v3.y; o3.z += pv*v3.z; o3.w += pv*v3.w;
        }
        __syncthreads();
    }

    float inv = 1.f / l_i;
    o0.x *= inv; o0.y *= inv; o0.z *= inv; o0.w *= inv;
    o1.x *= inv; o1.y *= inv; o1.z *= inv; o1.w *= inv;
    o2.x *= inv; o2.y *= inv; o2.z *= inv; o2.w *= inv;
    o3.x *= inv; o3.y *= inv; o3.z *= inv; o3.w *= inv;
    float* Op = O + ((size_t)((b * SEQ + qg) * NH + h)) * HD;
    *(float4*)(Op + 4 * lg)      = o0;
    *(float4*)(Op + 4 * lg + 32) = o1;
    *(float4*)(Op + 4 * lg + 64) = o2;
    *(float4*)(Op + 4 * lg + 96) = o3;
}

// ============================================================================
// launch
// ============================================================================
extern "C" void kernel_launch(void* const* d_in, const int* in_sizes, int n_in,
                              void* d_out, int out_size) {
    const float* x    = (const float*)d_in[0];
    const float* fcos = (const float*)d_in[1];
    const float* fsin = (const float*)d_in[2];
    // d_in[3] mask, d_in[4] input_idexes, d_in[5] cache_k, d_in[6] cache_v: unused
    const float* wq = (const float*)d_in[7];
    const float* wk = (const float*)d_in[8];
    const float* wv = (const float*)d_in[9];
    const float* wo = (const float*)d_in[10];

    float* out     = (float*)d_out;                               // [B,S,DIM]
    float* cache_k = (float*)d_out + (size_t)NTOK * DIM;          // [B,S,NH,HD]
    float* cache_v = (float*)d_out + (size_t)2 * NTOK * DIM;      // [B,S,NH,HD]

    float* qbuf; cudaGetSymbolAddress((void**)&qbuf, g_q);
    float* abuf; cudaGetSymbolAddress((void**)&abuf, g_att);

    cudaFuncSetAttribute(flash_attn, cudaFuncAttributeMaxDynamicSharedMemorySize, FA_SMEM);

    dim3 gg(DIM / 128, NTOK / 128);   // (32, 32)
    gemm_mma<<<gg, 256>>>(x, wq, qbuf);
    gemm_mma<<<gg, 256>>>(x, wk, cache_k);
    gemm_mma<<<gg, 256>>>(x, wv, cache_v);

    rope_kernel<<<(NTOK * NH * 64) / 256, 256>>>(qbuf, cache_k, fcos, fsin);

    dim3 fg(SEQ / BQ, NH, BSZ);
    flash_attn<<<fg, 256, FA_SMEM>>>(qbuf, cache_k, cache_v, abuf);

    gemm_mma<<<gg, 256>>>(abuf, wo, out);
}

// round 4
// speedup vs baseline: 3.1212x; 1.7393x over previous
#include <cuda_runtime.h>
#include <math.h>
#include <stdint.h>

#define DIM   4096
#define NH    32
#define HD    128
#define BSZ   2
#define SEQ   2048
#define NTOK  (BSZ*SEQ)          // 4096 tokens

// ---------------- scratch (allocation-free: __device__ globals) -------------
__device__ float g_q[(size_t)NTOK * DIM];    // rotated Q, 64 MB
__device__ float g_att[(size_t)NTOK * DIM];  // attention output, 64 MB

// ============================================================================
// helpers
// ============================================================================
__device__ __forceinline__ uint32_t smem_u32(const void* p) {
    uint32_t a;
    asm("{ .reg .u64 t; cvta.to.shared.u64 t, %1; cvt.u32.u64 %0, t; }"
        : "=r"(a) : "l"(p));
    return a;
}

__device__ __forceinline__ void cp16(uint32_t dst, const void* src) {
    asm volatile("cp.async.cg.shared.global [%0], [%1], 16;" :: "r"(dst), "l"(src));
}
#define CP_COMMIT() asm volatile("cp.async.commit_group;" ::: "memory")
#define CP_WAIT0()  asm volatile("cp.async.wait_group 0;"  ::: "memory")

__device__ __forceinline__ uint32_t f2tf(float f) {
    uint32_t r;
    asm("cvt.rna.tf32.f32 %0, %1;" : "=r"(r) : "f"(f));
    return r;
}
__device__ __forceinline__ float f2tf_f(float f) { return __uint_as_float(f2tf(f)); }

__device__ __forceinline__ void mma16n8k8(float* c, const uint32_t* a, const uint32_t* b) {
    asm volatile(
        "mma.sync.aligned.m16n8k8.row.col.f32.tf32.tf32.f32 "
        "{%0,%1,%2,%3}, {%4,%5,%6,%7}, {%8,%9}, {%0,%1,%2,%3};"
        : "+f"(c[0]), "+f"(c[1]), "+f"(c[2]), "+f"(c[3])
        : "r"(a[0]), "r"(a[1]), "r"(a[2]), "r"(a[3]), "r"(b[0]), "r"(b[1]));
}

// ============================================================================
// tf32 mma.sync GEMM (NT): C[m,n] = sum_k A[m,k]*B[n,k];  M=N=K=4096
// CTA 256x128, 8 warps (4x2), warp tile 64x64, BK=16, cp.async double buffer.
// smem row stride 20 floats: all fragment LDS patterns are conflict-free.
// ============================================================================
#define GTM 256
#define GTN 128
#define GTS 20
#define GNKI (DIM / 16)                       // 256
#define G_SMEM ((2*GTM*GTS + 2*GTN*GTS) * 4)  // 61440 B

__global__ __launch_bounds__(256, 1) void gemm_mma(const float* __restrict__ A,
                                                   const float* __restrict__ B,
                                                   float* __restrict__ C) {
    extern __shared__ float smf[];
    float* As = smf;                       // [2][GTM*GTS]
    float* Bs = smf + 2 * GTM * GTS;       // [2][GTN*GTS]

    const int t    = threadIdx.x;
    const int lane = t & 31;
    const int w    = t >> 5;
    const int wm   = w >> 1;          // 0..3  (64-row slab)
    const int wn   = w & 1;           // 0..1  (64-col slab)
    const int g    = lane >> 2;       // 0..7
    const int q    = lane & 3;        // 0..3
    const int bm   = blockIdx.y, bn = blockIdx.x;

    const uint32_t sA = smem_u32(As), sB = smem_u32(Bs);
    const int ra = t >> 2;            // 0..63
    const int ca = (t & 3) * 4;       // 0,4,8,12
    const float* Agp = A + (size_t)(bm * GTM) * DIM;
    const float* Bgp = B + (size_t)(bn * GTN) * DIM;

    float acc[4][8][4];
#pragma unroll
    for (int i = 0; i < 4; i++)
#pragma unroll
        for (int j = 0; j < 8; j++)
#pragma unroll
            for (int v = 0; v < 4; v++) acc[i][j][v] = 0.f;

    // prefetch tile 0
    {
        const uint32_t dA = sA, dB = sB;
#pragma unroll
        for (int j = 0; j < 4; j++) {
            int row = ra + j * 64;
            cp16(dA + (row * GTS + ca) * 4, Agp + (size_t)row * DIM + ca);
        }
#pragma unroll
        for (int j = 0; j < 2; j++) {
            int row = ra + j * 64;
            cp16(dB + (row * GTS + ca) * 4, Bgp + (size_t)row * DIM + ca);
        }
        CP_COMMIT();
    }

    for (int i = 0; i < GNKI; i++) {
        const int buf = i & 1;
        CP_WAIT0();
        __syncthreads();

        if (i + 1 < GNKI) {
            const int nb = buf ^ 1;
            const int k0 = (i + 1) * 16;
            const uint32_t dA = sA + nb * (GTM * GTS * 4);
            const uint32_t dB = sB + nb * (GTN * GTS * 4);
#pragma unroll
            for (int j = 0; j < 4; j++) {
                int row = ra + j * 64;
                cp16(dA + (row * GTS + ca) * 4, Agp + (size_t)row * DIM + k0 + ca);
            }
#pragma unroll
            for (int j = 0; j < 2; j++) {
                int row = ra + j * 64;
                cp16(dB + (row * GTS + ca) * 4, Bgp + (size_t)row * DIM + k0 + ca);
            }
            CP_COMMIT();
        }

        const float* Ab = As + buf * (GTM * GTS);
        const float* Bb = Bs + buf * (GTN * GTS);
#pragma unroll
        for (int k8 = 0; k8 < 2; k8++) {
            const int kc = k8 * 8 + q;
            uint32_t af[4][4], bf[8][2];
#pragma unroll
            for (int mt = 0; mt < 4; mt++) {
                const int r0 = wm * 64 + mt * 16 + g;
                af[mt][0] = f2tf(Ab[r0 * GTS + kc]);
                af[mt][1] = f2tf(Ab[(r0 + 8) * GTS + kc]);
                af[mt][2] = f2tf(Ab[r0 * GTS + kc + 4]);
                af[mt][3] = f2tf(Ab[(r0 + 8) * GTS + kc + 4]);
            }
#pragma unroll
            for (int nt = 0; nt < 8; nt++) {
                const int c0 = wn * 64 + nt * 8 + g;
                bf[nt][0] = f2tf(Bb[c0 * GTS + kc]);
                bf[nt][1] = f2tf(Bb[c0 * GTS + kc + 4]);
            }
#pragma unroll
            for (int mt = 0; mt < 4; mt++)
#pragma unroll
                for (int nt = 0; nt < 8; nt++)
                    mma16n8k8(acc[mt][nt], af[mt], bf[nt]);
        }
        __syncthreads();
    }

    // epilogue
#pragma unroll
    for (int mt = 0; mt < 4; mt++) {
        const size_t row = (size_t)bm * GTM + wm * 64 + mt * 16 + g;
#pragma unroll
        for (int nt = 0; nt < 8; nt++) {
            const int col = bn * GTN + wn * 64 + nt * 8 + q * 2;
            float2 v0 = {acc[mt][nt][0], acc[mt][nt][1]};
            float2 v1 = {acc[mt][nt][2], acc[mt][nt][3]};
            *(float2*)(C + row * DIM + col)       = v0;
            *(float2*)(C + (row + 8) * DIM + col) = v1;
        }
    }
}

// ============================================================================
// RoPE: rotate pairs in q (g_q) and k (cache_k region of d_out) in place.
// ============================================================================
__global__ void rope_kernel(float* __restrict__ q, float* __restrict__ k,
                            const float* __restrict__ cs, const float* __restrict__ sn) {
    int idx = blockIdx.x * blockDim.x + threadIdx.x;
    int i = idx & 63;
    int s = (idx >> 11) & 2047;
    float cv = cs[s * 64 + i];
    float sv = sn[s * 64 + i];
    int h = (idx >> 6) & 31;
    int b = idx >> 22;
    size_t base = ((size_t)((b * SEQ + s) * NH) + h) * HD + 2 * i;
    float2 qv = *(float2*)(q + base);
    float2 kv = *(float2*)(k + base);
    float2 qo, ko;
    qo.x = qv.x * cv - qv.y * sv;  qo.y = qv.x * sv + qv.y * cv;
    ko.x = kv.x * cv - kv.y * sv;  ko.y = kv.x * sv + kv.y * cv;
    *(float2*)(q + base) = qo;
    *(float2*)(k + base) = ko;
}

// ============================================================================
// Tensor-core flash attention (tf32 mma.sync): BQ=128, BK=64, 8 warps.
// All smem operands pre-rounded to tf32 at load; no cvt in mainloop.
// Q/K stride 132, V stride 136, P stride 68: bank-conflict-free fragments.
// ============================================================================
#define ABQ 128
#define ABK 64
#define AQS 132
#define AKS 132
#define AVS 136
#define APS 68
#define FA_SMEM ((ABQ*AQS + ABK*AKS + ABK*AVS + 8*16*APS) * 4)   // 171008 B

__global__ __launch_bounds__(256, 1) void flash_mma(const float* __restrict__ Q,
                                                    const float* __restrict__ Kc,
                                                    const float* __restrict__ Vc,
                                                    float* __restrict__ O) {
    extern __shared__ float sm[];
    float* Qs = sm;                         // 128 x 132
    float* Ks = Qs + ABQ * AQS;             // 64 x 132
    float* Vs = Ks + ABK * AKS;             // 64 x 136
    float* Ps = Vs + ABK * AVS;             // 8 warps x 16 x 68

    const int t    = threadIdx.x;
    const int w    = t >> 5;
    const int lane = t & 31;
    const int g    = lane >> 2;
    const int q    = lane & 3;
    const int qt   = gridDim.x - 1 - blockIdx.x;   // longest tiles first
    const int h    = blockIdx.y, b = blockIdx.z;
    const float scale = 0.08838834764831845f;      // 1/sqrt(128)

    // load Q tile (tf32-rounded)
    for (int i = t; i < ABQ * 32; i += 256) {
        int row = i >> 5, c4 = i & 31;
        const float4 v = *(const float4*)(Q + ((size_t)((b * SEQ + qt * ABQ + row) * NH + h)) * HD + c4 * 4);
        float* d = Qs + row * AQS + c4 * 4;
        d[0] = f2tf_f(v.x); d[1] = f2tf_f(v.y); d[2] = f2tf_f(v.z); d[3] = f2tf_f(v.w);
    }

    float o[16][4];
#pragma unroll
    for (int i = 0; i < 16; i++)
#pragma unroll
        for (int v = 0; v < 4; v++) o[i][v] = 0.f;
    float mA = -INFINITY, mB = -INFINITY, lA = 0.f, lB = 0.f;

    float* Pw = Ps + w * 16 * APS;
    const int r0   = w * 16;
    const int rowA = qt * ABQ + r0 + g;            // rowB = rowA + 8
    const int nkb  = 2 * (qt + 1);
    __syncthreads();

    for (int kb = 0; kb < nkb; kb++) {
        // load K/V tile (tf32-rounded)
        for (int i = t; i < ABK * 32; i += 256) {
            int row = i >> 5, c4 = i & 31;
            size_t gk = ((size_t)((b * SEQ + kb * ABK + row) * NH + h)) * HD + c4 * 4;
            const float4 kv = *(const float4*)(Kc + gk);
            const float4 vv = *(const float4*)(Vc + gk);
            float* dk = Ks + row * AKS + c4 * 4;
            float* dv = Vs + row * AVS + c4 * 4;
            dk[0] = f2tf_f(kv.x); dk[1] = f2tf_f(kv.y); dk[2] = f2tf_f(kv.z); dk[3] = f2tf_f(kv.w);
            dv[0] = f2tf_f(vv.x); dv[1] = f2tf_f(vv.y); dv[2] = f2tf_f(vv.z); dv[3] = f2tf_f(vv.w);
        }
        __syncthreads();

        const bool full_skip = (kb * ABK > qt * ABQ + r0 + 15);
        if (!full_skip) {
            // ---- S = Q K^T (warp rows r0..r0+15, all 64 key cols) ----
            float s[8][4];
#pragma unroll
            for (int i = 0; i < 8; i++)
#pragma unroll
                for (int v = 0; v < 4; v++) s[i][v] = 0.f;
#pragma unroll
            for (int k8 = 0; k8 < 16; k8++) {
                const int kc = k8 * 8 + q;
                uint32_t a[4];
                a[0] = __float_as_uint(Qs[(r0 + g) * AQS + kc]);
                a[1] = __float_as_uint(Qs[(r0 + g + 8) * AQS + kc]);
                a[2] = __float_as_uint(Qs[(r0 + g) * AQS + kc + 4]);
                a[3] = __float_as_uint(Qs[(r0 + g + 8) * AQS + kc + 4]);
#pragma unroll
                for (int nt = 0; nt < 8; nt++) {
                    uint32_t bfr[2];
                    bfr[0] = __float_as_uint(Ks[(nt * 8 + g) * AKS + kc]);
                    bfr[1] = __float_as_uint(Ks[(nt * 8 + g) * AKS + kc + 4]);
                    mma16n8k8(s[nt], a, bfr);
                }
            }
            // ---- scale + causal mask ----
            const bool need_mask = (kb * ABK + ABK - 1 > qt * ABQ + r0);
#pragma unroll
            for (int nt = 0; nt < 8; nt++) {
                const int c0 = kb * ABK + nt * 8 + 2 * q;
                s[nt][0] *= scale; s[nt][1] *= scale;
                s[nt][2] *= scale; s[nt][3] *= scale;
                if (need_mask) {
                    if (c0     > rowA)     s[nt][0] = -1e30f;
                    if (c0 + 1 > rowA)     s[nt][1] = -1e30f;
                    if (c0     > rowA + 8) s[nt][2] = -1e30f;
                    if (c0 + 1 > rowA + 8) s[nt][3] = -1e30f;
                }
            }
            // ---- online softmax (rows g and g+8) ----
            float mxA = -INFINITY, mxB = -INFINITY;
#pragma unroll
            for (int nt = 0; nt < 8; nt++) {
                mxA = fmaxf(mxA, fmaxf(s[nt][0], s[nt][1]));
                mxB = fmaxf(mxB, fmaxf(s[nt][2], s[nt][3]));
            }
            mxA = fmaxf(mxA, __shfl_xor_sync(0xffffffffu, mxA, 1));
            mxA = fmaxf(mxA, __shfl_xor_sync(0xffffffffu, mxA, 2));
            mxB = fmaxf(mxB, __shfl_xor_sync(0xffffffffu, mxB, 1));
            mxB = fmaxf(mxB, __shfl_xor_sync(0xffffffffu, mxB, 2));
            const float mnA = fmaxf(mA, mxA), mnB = fmaxf(mB, mxB);
            const float aA = __expf(mA - mnA), aB = __expf(mB - mnB);
            float sumA = 0.f, sumB = 0.f;
#pragma unroll
            for (int nt = 0; nt < 8; nt++) {
                float p0 = __expf(s[nt][0] - mnA), p1 = __expf(s[nt][1] - mnA);
                float p2 = __expf(s[nt][2] - mnB), p3 = __expf(s[nt][3] - mnB);
                sumA += p0 + p1; sumB += p2 + p3;
                float2 pa = {f2tf_f(p0), f2tf_f(p1)};
                float2 pb = {f2tf_f(p2), f2tf_f(p3)};
                *(float2*)(Pw + g * APS + nt * 8 + 2 * q)       = pa;
                *(float2*)(Pw + (g + 8) * APS + nt * 8 + 2 * q) = pb;
            }
            sumA += __shfl_xor_sync(0xffffffffu, sumA, 1);
            sumA += __shfl_xor_sync(0xffffffffu, sumA, 2);
            sumB += __shfl_xor_sync(0xffffffffu, sumB, 1);
            sumB += __shfl_xor_sync(0xffffffffu, sumB, 2);
            lA = lA * aA + sumA;  mA = mnA;
            lB = lB * aB + sumB;  mB = mnB;
#pragma unroll
            for (int nt = 0; nt < 16; nt++) {
                o[nt][0] *= aA; o[nt][1] *= aA;
                o[nt][2] *= aB; o[nt][3] *= aB;
            }
            __syncwarp();
            // ---- O += P V ----
#pragma unroll
            for (int k8 = 0; k8 < 8; k8++) {
                const int kc = k8 * 8 + q;
                uint32_t a[4];
                a[0] = __float_as_uint(Pw[g * APS + kc]);
                a[1] = __float_as_uint(Pw[(g + 8) * APS + kc]);
                a[2] = __float_as_uint(Pw[g * APS + kc + 4]);
                a[3] = __float_as_uint(Pw[(g + 8) * APS + kc + 4]);
#pragma unroll
                for (int nt = 0; nt < 16; nt++) {
                    uint32_t bfr[2];
                    bfr[0] = __float_as_uint(Vs[kc * AVS + nt * 8 + g]);
                    bfr[1] = __float_as_uint(Vs[(kc + 4) * AVS + nt * 8 + g]);
                    mma16n8k8(o[nt], a, bfr);
                }
            }
        }
        __syncthreads();
    }

    const float invA = 1.f / lA, invB = 1.f / lB;
    const size_t baseA = ((size_t)((b * SEQ + rowA) * NH + h)) * HD;
    const size_t baseB = baseA + (size_t)8 * NH * HD;
#pragma unroll
    for (int nt = 0; nt < 16; nt++) {
        float2 va = {o[nt][0] * invA, o[nt][1] * invA};
        float2 vb = {o[nt][2] * invB, o[nt][3] * invB};
        *(float2*)(O + baseA + nt * 8 + 2 * q) = va;
        *(float2*)(O + baseB + nt * 8 + 2 * q) = vb;
    }
}

// ============================================================================
// launch
// ============================================================================
extern "C" void kernel_launch(void* const* d_in, const int* in_sizes, int n_in,
                              void* d_out, int out_size) {
    const float* x    = (const float*)d_in[0];
    const float* fcos = (const float*)d_in[1];
    const float* fsin = (const float*)d_in[2];
    // d_in[3] mask, d_in[4] input_idexes, d_in[5] cache_k, d_in[6] cache_v: unused
    const float* wq = (const float*)d_in[7];
    const float* wk = (const float*)d_in[8];
    const float* wv = (const float*)d_in[9];
    const float* wo = (const float*)d_in[10];

    float* out     = (float*)d_out;                               // [B,S,DIM]
    float* cache_k = (float*)d_out + (size_t)NTOK * DIM;          // [B,S,NH,HD]
    float* cache_v = (float*)d_out + (size_t)2 * NTOK * DIM;      // [B,S,NH,HD]

    float* qbuf; cudaGetSymbolAddress((void**)&qbuf, g_q);
    float* abuf; cudaGetSymbolAddress((void**)&abuf, g_att);

    cudaFuncSetAttribute(gemm_mma,  cudaFuncAttributeMaxDynamicSharedMemorySize, G_SMEM);
    cudaFuncSetAttribute(flash_mma, cudaFuncAttributeMaxDynamicSharedMemorySize, FA_SMEM);

    dim3 gg(DIM / GTN, NTOK / GTM);   // (32, 16)
    gemm_mma<<<gg, 256, G_SMEM>>>(x, wq, qbuf);
    gemm_mma<<<gg, 256, G_SMEM>>>(x, wk, cache_k);
    gemm_mma<<<gg, 256, G_SMEM>>>(x, wv, cache_v);

    rope_kernel<<<(NTOK * NH * 64) / 256, 256>>>(qbuf, cache_k, fcos, fsin);

    dim3 fg(SEQ / ABQ, NH, BSZ);      // (16, 32, 2)
    flash_mma<<<fg, 256, FA_SMEM>>>(qbuf, cache_k, cache_v, abuf);

    gemm_mma<<<gg, 256, G_SMEM>>>(abuf, wo, out);
}

// round 5
// speedup vs baseline: 3.2396x; 1.0379x over previous
#include <cuda_runtime.h>
#include <math.h>
#include <stdint.h>

#define DIM   4096
#define NH    32
#define HD    128
#define BSZ   2
#define SEQ   2048
#define NTOK  (BSZ*SEQ)          // 4096 tokens

// ---------------- scratch (allocation-free: __device__ globals) -------------
__device__ float g_q[(size_t)NTOK * DIM];    // rotated Q, 64 MB
__device__ float g_att[(size_t)NTOK * DIM];  // attention output, 64 MB

// ============================================================================
// helpers
// ============================================================================
__device__ __forceinline__ uint32_t smem_u32(const void* p) {
    uint32_t a;
    asm("{ .reg .u64 t; cvta.to.shared.u64 t, %1; cvt.u32.u64 %0, t; }"
        : "=r"(a) : "l"(p));
    return a;
}

__device__ __forceinline__ void cp16(uint32_t dst, const void* src) {
    asm volatile("cp.async.cg.shared.global [%0], [%1], 16;" :: "r"(dst), "l"(src));
}
#define CP_COMMIT() asm volatile("cp.async.commit_group;" ::: "memory")
#define CP_WAIT1()  asm volatile("cp.async.wait_group 1;"  ::: "memory")
#define CP_WAIT2()  asm volatile("cp.async.wait_group 2;"  ::: "memory")

__device__ __forceinline__ uint32_t f2tf(float f) {
    uint32_t r;
    asm("cvt.rna.tf32.f32 %0, %1;" : "=r"(r) : "f"(f));
    return r;
}
__device__ __forceinline__ float f2tf_f(float f) { return __uint_as_float(f2tf(f)); }

__device__ __forceinline__ void mma16n8k8(float* c, const uint32_t* a, const uint32_t* b) {
    asm volatile(
        "mma.sync.aligned.m16n8k8.row.col.f32.tf32.tf32.f32 "
        "{%0,%1,%2,%3}, {%4,%5,%6,%7}, {%8,%9}, {%0,%1,%2,%3};"
        : "+f"(c[0]), "+f"(c[1]), "+f"(c[2]), "+f"(c[3])
        : "r"(a[0]), "r"(a[1]), "r"(a[2]), "r"(a[3]), "r"(b[0]), "r"(b[1]));
}

// ============================================================================
// tf32 mma.sync GEMM (NT): C[m,n] = sum_k A[m,k]*B[n,k];  M=N=K=4096
// CTA 256x128, 8 warps (4x2), warp tile 64x64, BK=16, 4-stage cp.async pipe.
// Optional fused RoPE in the epilogue (rcs/rsn != null).
// ============================================================================
#define GTM 256
#define GTN 128
#define GTS 20
#define GST 4
#define GNKI (DIM / 16)                              // 256
#define G_SMEM ((GST*GTM*GTS + GST*GTN*GTS) * 4)     // 122880 B

__global__ __launch_bounds__(256, 1) void gemm_mma(const float* __restrict__ A,
                                                   const float* __restrict__ B,
                                                   float* __restrict__ C,
                                                   const float* __restrict__ rcs,
                                                   const float* __restrict__ rsn) {
    extern __shared__ float smf[];
    float* As = smf;                           // [GST][GTM*GTS]
    float* Bs = smf + GST * GTM * GTS;         // [GST][GTN*GTS]

    const int t    = threadIdx.x;
    const int lane = t & 31;
    const int w    = t >> 5;
    const int wm   = w >> 1;          // 0..3  (64-row slab)
    const int wn   = w & 1;           // 0..1  (64-col slab)
    const int g    = lane >> 2;       // 0..7
    const int q    = lane & 3;        // 0..3
    const int bm   = blockIdx.y, bn = blockIdx.x;

    const uint32_t sA = smem_u32(As), sB = smem_u32(Bs);
    const int ra = t >> 2;            // 0..63
    const int ca = (t & 3) * 4;       // 0,4,8,12
    const float* Agp = A + (size_t)(bm * GTM) * DIM;
    const float* Bgp = B + (size_t)(bn * GTN) * DIM;

    float acc[4][8][4];
#pragma unroll
    for (int i = 0; i < 4; i++)
#pragma unroll
        for (int j = 0; j < 8; j++)
#pragma unroll
            for (int v = 0; v < 4; v++) acc[i][j][v] = 0.f;

    // prologue: stages 0..2
#pragma unroll
    for (int s = 0; s < GST - 1; s++) {
        const int k0 = s * 16;
        const uint32_t dA = sA + s * (GTM * GTS * 4);
        const uint32_t dB = sB + s * (GTN * GTS * 4);
#pragma unroll
        for (int j = 0; j < 4; j++) {
            int row = ra + j * 64;
            cp16(dA + (row * GTS + ca) * 4, Agp + (size_t)row * DIM + k0 + ca);
        }
#pragma unroll
        for (int j = 0; j < 2; j++) {
            int row = ra + j * 64;
            cp16(dB + (row * GTS + ca) * 4, Bgp + (size_t)row * DIM + k0 + ca);
        }
        CP_COMMIT();
    }

    for (int i = 0; i < GNKI; i++) {
        CP_WAIT2();
        __syncthreads();

        if (i + GST - 1 < GNKI) {
            const int st = (i + GST - 1) & (GST - 1);
            const int k0 = (i + GST - 1) * 16;
            const uint32_t dA = sA + st * (GTM * GTS * 4);
            const uint32_t dB = sB + st * (GTN * GTS * 4);
#pragma unroll
            for (int j = 0; j < 4; j++) {
                int row = ra + j * 64;
                cp16(dA + (row * GTS + ca) * 4, Agp + (size_t)row * DIM + k0 + ca);
            }
#pragma unroll
            for (int j = 0; j < 2; j++) {
                int row = ra + j * 64;
                cp16(dB + (row * GTS + ca) * 4, Bgp + (size_t)row * DIM + k0 + ca);
            }
        }
        CP_COMMIT();   // always commit (empty in tail) to keep group counts valid

        const float* Ab = As + (i & (GST - 1)) * (GTM * GTS);
        const float* Bb = Bs + (i & (GST - 1)) * (GTN * GTS);
#pragma unroll
        for (int k8 = 0; k8 < 2; k8++) {
            const int kc = k8 * 8 + q;
            uint32_t af[4][4], bf[8][2];
#pragma unroll
            for (int mt = 0; mt < 4; mt++) {
                const int r0 = wm * 64 + mt * 16 + g;
                af[mt][0] = f2tf(Ab[r0 * GTS + kc]);
                af[mt][1] = f2tf(Ab[(r0 + 8) * GTS + kc]);
                af[mt][2] = f2tf(Ab[r0 * GTS + kc + 4]);
                af[mt][3] = f2tf(Ab[(r0 + 8) * GTS + kc + 4]);
            }
#pragma unroll
            for (int nt = 0; nt < 8; nt++) {
                const int c0 = wn * 64 + nt * 8 + g;
                bf[nt][0] = f2tf(Bb[c0 * GTS + kc]);
                bf[nt][1] = f2tf(Bb[c0 * GTS + kc + 4]);
            }
#pragma unroll
            for (int mt = 0; mt < 4; mt++)
#pragma unroll
                for (int nt = 0; nt < 8; nt++)
                    mma16n8k8(acc[mt][nt], af[mt], bf[nt]);
        }
    }

    // epilogue (optionally fused RoPE: accumulator col pairs ARE rotary pairs)
    const bool do_rope = (rcs != nullptr);
#pragma unroll
    for (int mt = 0; mt < 4; mt++) {
        const size_t row = (size_t)bm * GTM + wm * 64 + mt * 16 + g;
#pragma unroll
        for (int nt = 0; nt < 8; nt++) {
            const int col = bn * GTN + wn * 64 + nt * 8 + q * 2;
            float2 v0 = {acc[mt][nt][0], acc[mt][nt][1]};
            float2 v1 = {acc[mt][nt][2], acc[mt][nt][3]};
            if (do_rope) {
                const int fi = (col & 127) >> 1;
                const int s0 = (int)(row & (SEQ - 1));
                const int s1 = (int)((row + 8) & (SEQ - 1));
                float c0 = rcs[s0 * 64 + fi], sn0 = rsn[s0 * 64 + fi];
                float c1 = rcs[s1 * 64 + fi], sn1 = rsn[s1 * 64 + fi];
                float2 r0 = {v0.x * c0 - v0.y * sn0, v0.x * sn0 + v0.y * c0};
                float2 r1 = {v1.x * c1 - v1.y * sn1, v1.x * sn1 + v1.y * c1};
                v0 = r0; v1 = r1;
            }
            *(float2*)(C + row * DIM + col)       = v0;
            *(float2*)(C + (row + 8) * DIM + col) = v1;
        }
    }
}

// ============================================================================
// Tensor-core flash attention (tf32 mma.sync): BQ=128, BK=64, 8 warps.
// K double-buffered + V single-buffered cp.async pipeline; raw tiles are
// tf32-converted in place by the issuing thread (self-owned chunks).
// ============================================================================
#define ABQ 128
#define ABK 64
#define AQS 132
#define AKS 132
#define AVS 136
#define APS 68
#define FA_SMEM ((ABQ*AQS + 2*ABK*AKS + ABK*AVS + 8*16*APS) * 4)   // 204800 B

__global__ __launch_bounds__(256, 1) void flash_mma(const float* __restrict__ Q,
                                                    const float* __restrict__ Kc,
                                                    const float* __restrict__ Vc,
                                                    float* __restrict__ O) {
    extern __shared__ float sm[];
    float* Qs = sm;                              // 128 x 132
    float* Kb = Qs + ABQ * AQS;                  // 2 x (64 x 132)
    float* Vs = Kb + 2 * ABK * AKS;              // 64 x 136
    float* Ps = Vs + ABK * AVS;                  // 8 warps x 16 x 68

    const int t    = threadIdx.x;
    const int w    = t >> 5;
    const int lane = t & 31;
    const int g    = lane >> 2;
    const int q    = lane & 3;
    const int qt   = gridDim.x - 1 - blockIdx.x;   // longest tiles first
    const int h    = blockIdx.y, b = blockIdx.z;
    const float scale = 0.08838834764831845f;      // 1/sqrt(128)

    const uint32_t sKb = smem_u32(Kb);
    const uint32_t sVs = smem_u32(Vs);
    const int nkb = 2 * (qt + 1);

    // issue one K tile (raw) into K buffer `buf`
    auto issueK = [&](int kb, int buf) {
        const uint32_t base = sKb + (uint32_t)buf * (ABK * AKS * 4);
        for (int i = t; i < ABK * 32; i += 256) {
            int row = i >> 5, c4 = i & 31;
            size_t gk = ((size_t)((b * SEQ + kb * ABK + row) * NH + h)) * HD + c4 * 4;
            cp16(base + (row * AKS + c4 * 4) * 4, Kc + gk);
        }
    };
    auto issueV = [&](int kb) {
        for (int i = t; i < ABK * 32; i += 256) {
            int row = i >> 5, c4 = i & 31;
            size_t gk = ((size_t)((b * SEQ + kb * ABK + row) * NH + h)) * HD + c4 * 4;
            cp16(sVs + (row * AVS + c4 * 4) * 4, Vc + gk);
        }
    };

    // load Q tile (tf32-rounded) + prologue K0/V0
    issueK(0, 0); CP_COMMIT();
    issueV(0);    CP_COMMIT();
    for (int i = t; i < ABQ * 32; i += 256) {
        int row = i >> 5, c4 = i & 31;
        const float4 v = *(const float4*)(Q + ((size_t)((b * SEQ + qt * ABQ + row) * NH + h)) * HD + c4 * 4);
        float* d = Qs + row * AQS + c4 * 4;
        d[0] = f2tf_f(v.x); d[1] = f2tf_f(v.y); d[2] = f2tf_f(v.z); d[3] = f2tf_f(v.w);
    }

    float o[16][4];
#pragma unroll
    for (int i = 0; i < 16; i++)
#pragma unroll
        for (int v = 0; v < 4; v++) o[i][v] = 0.f;
    float mA = -INFINITY, mB = -INFINITY, lA = 0.f, lB = 0.f;

    float* Pw = Ps + w * 16 * APS;
    const int r0   = w * 16;
    const int rowA = qt * ABQ + r0 + g;            // rowB = rowA + 8
    __syncthreads();

    for (int kb = 0; kb < nkb; kb++) {
        // prefetch next K while this tile computes
        if (kb + 1 < nkb) issueK(kb + 1, (kb + 1) & 1);
        CP_COMMIT();
        CP_WAIT1();          // K_kb and V_kb (this thread's own chunks) landed

        // in-place tf32 conversion of self-owned chunks
        float* Kcur = Kb + (kb & 1) * (ABK * AKS);
        for (int i = t; i < ABK * 32; i += 256) {
            int row = i >> 5, c4 = i & 31;
            float4* pk = (float4*)(Kcur + row * AKS + c4 * 4);
            float4 kv = *pk;
            kv.x = f2tf_f(kv.x); kv.y = f2tf_f(kv.y); kv.z = f2tf_f(kv.z); kv.w = f2tf_f(kv.w);
            *pk = kv;
            float4* pv = (float4*)(Vs + row * AVS + c4 * 4);
            float4 vv = *pv;
            vv.x = f2tf_f(vv.x); vv.y = f2tf_f(vv.y); vv.z = f2tf_f(vv.z); vv.w = f2tf_f(vv.w);
            *pv = vv;
        }
        __syncthreads();

        const bool full_skip = (kb * ABK > qt * ABQ + r0 + 15);
        if (!full_skip) {
            // ---- S = Q K^T ----
            float s[8][4];
#pragma unroll
            for (int i = 0; i < 8; i++)
#pragma unroll
                for (int v = 0; v < 4; v++) s[i][v] = 0.f;
#pragma unroll
            for (int k8 = 0; k8 < 16; k8++) {
                const int kc = k8 * 8 + q;
                uint32_t a[4];
                a[0] = __float_as_uint(Qs[(r0 + g) * AQS + kc]);
                a[1] = __float_as_uint(Qs[(r0 + g + 8) * AQS + kc]);
                a[2] = __float_as_uint(Qs[(r0 + g) * AQS + kc + 4]);
                a[3] = __float_as_uint(Qs[(r0 + g + 8) * AQS + kc + 4]);
#pragma unroll
                for (int nt = 0; nt < 8; nt++) {
                    uint32_t bfr[2];
                    bfr[0] = __float_as_uint(Kcur[(nt * 8 + g) * AKS + kc]);
                    bfr[1] = __float_as_uint(Kcur[(nt * 8 + g) * AKS + kc + 4]);
                    mma16n8k8(s[nt], a, bfr);
                }
            }
            // ---- scale + causal mask ----
            const bool need_mask = (kb * ABK + ABK - 1 > qt * ABQ + r0);
#pragma unroll
            for (int nt = 0; nt < 8; nt++) {
                const int c0 = kb * ABK + nt * 8 + 2 * q;
                s[nt][0] *= scale; s[nt][1] *= scale;
                s[nt][2] *= scale; s[nt][3] *= scale;
                if (need_mask) {
                    if (c0     > rowA)     s[nt][0] = -1e30f;
                    if (c0 + 1 > rowA)     s[nt][1] = -1e30f;
                    if (c0     > rowA + 8) s[nt][2] = -1e30f;
                    if (c0 + 1 > rowA + 8) s[nt][3] = -1e30f;
                }
            }
            // ---- online softmax ----
            float mxA = -INFINITY, mxB = -INFINITY;
#pragma unroll
            for (int nt = 0; nt < 8; nt++) {
                mxA = fmaxf(mxA, fmaxf(s[nt][0], s[nt][1]));
                mxB = fmaxf(mxB, fmaxf(s[nt][2], s[nt][3]));
            }
            mxA = fmaxf(mxA, __shfl_xor_sync(0xffffffffu, mxA, 1));
            mxA = fmaxf(mxA, __shfl_xor_sync(0xffffffffu, mxA, 2));
            mxB = fmaxf(mxB, __shfl_xor_sync(0xffffffffu, mxB, 1));
            mxB = fmaxf(mxB, __shfl_xor_sync(0xffffffffu, mxB, 2));
            const float mnA = fmaxf(mA, mxA), mnB = fmaxf(mB, mxB);
            const float aA = __expf(mA - mnA), aB = __expf(mB - mnB);
            float sumA = 0.f, sumB = 0.f;
#pragma unroll
            for (int nt = 0; nt < 8; nt++) {
                float p0 = __expf(s[nt][0] - mnA), p1 = __expf(s[nt][1] - mnA);
                float p2 = __expf(s[nt][2] - mnB), p3 = __expf(s[nt][3] - mnB);
                sumA += p0 + p1; sumB += p2 + p3;
                float2 pa = {f2tf_f(p0), f2tf_f(p1)};
                float2 pb = {f2tf_f(p2), f2tf_f(p3)};
                *(float2*)(Pw + g * APS + nt * 8 + 2 * q)       = pa;
                *(float2*)(Pw + (g + 8) * APS + nt * 8 + 2 * q) = pb;
            }
            sumA += __shfl_xor_sync(0xffffffffu, sumA, 1);
            sumA += __shfl_xor_sync(0xffffffffu, sumA, 2);
            sumB += __shfl_xor_sync(0xffffffffu, sumB, 1);
            sumB += __shfl_xor_sync(0xffffffffu, sumB, 2);
            lA = lA * aA + sumA;  mA = mnA;
            lB = lB * aB + sumB;  mB = mnB;
#pragma unroll
            for (int nt = 0; nt < 16; nt++) {
                o[nt][0] *= aA; o[nt][1] *= aA;
                o[nt][2] *= aB; o[nt][3] *= aB;
            }
            __syncwarp();
            // ---- O += P V ----
#pragma unroll
            for (int k8 = 0; k8 < 8; k8++) {
                const int kc = k8 * 8 + q;
                uint32_t a[4];
                a[0] = __float_as_uint(Pw[g * APS + kc]);
                a[1] = __float_as_uint(Pw[(g + 8) * APS + kc]);
                a[2] = __float_as_uint(Pw[g * APS + kc + 4]);
                a[3] = __float_as_uint(Pw[(g + 4 + 4) * APS + kc + 4]);
#pragma unroll
                for (int nt = 0; nt < 16; nt++) {
                    uint32_t bfr[2];
                    bfr[0] = __float_as_uint(Vs[kc * AVS + nt * 8 + g]);
                    bfr[1] = __float_as_uint(Vs[(kc + 4) * AVS + nt * 8 + g]);
                    mma16n8k8(o[nt], a, bfr);
                }
            }
        }
        __syncthreads();     // everyone done with Vs before refill

        if (kb + 1 < nkb) issueV(kb + 1);
        CP_COMMIT();
    }

    const float invA = 1.f / lA, invB = 1.f / lB;
    const size_t baseA = ((size_t)((b * SEQ + rowA) * NH + h)) * HD;
    const size_t baseB = baseA + (size_t)8 * NH * HD;
#pragma unroll
    for (int nt = 0; nt < 16; nt++) {
        float2 va = {o[nt][0] * invA, o[nt][1] * invA};
        float2 vb = {o[nt][2] * invB, o[nt][3] * invB};
        *(float2*)(O + baseA + nt * 8 + 2 * q) = va;
        *(float2*)(O + baseB + nt * 8 + 2 * q) = vb;
    }
}

// ============================================================================
// launch
// ============================================================================
extern "C" void kernel_launch(void* const* d_in, const int* in_sizes, int n_in,
                              void* d_out, int out_size) {
    const float* x    = (const float*)d_in[0];
    const float* fcos = (const float*)d_in[1];
    const float* fsin = (const float*)d_in[2];
    // d_in[3] mask, d_in[4] input_idexes, d_in[5] cache_k, d_in[6] cache_v: unused
    const float* wq = (const float*)d_in[7];
    const float* wk = (const float*)d_in[8];
    const float* wv = (const float*)d_in[9];
    const float* wo = (const float*)d_in[10];

    float* out     = (float*)d_out;                               // [B,S,DIM]
    float* cache_k = (float*)d_out + (size_t)NTOK * DIM;          // [B,S,NH,HD]
    float* cache_v = (float*)d_out + (size_t)2 * NTOK * DIM;      // [B,S,NH,HD]

    float* qbuf; cudaGetSymbolAddress((void**)&qbuf, g_q);
    float* abuf; cudaGetSymbolAddress((void**)&abuf, g_att);

    cudaFuncSetAttribute(gemm_mma,  cudaFuncAttributeMaxDynamicSharedMemorySize, G_SMEM);
    cudaFuncSetAttribute(flash_mma, cudaFuncAttributeMaxDynamicSharedMemorySize, FA_SMEM);

    dim3 gg(DIM / GTN, NTOK / GTM);   // (32, 16)
    gemm_mma<<<gg, 256, G_SMEM>>>(x, wq, qbuf,    fcos, fsin);   // fused RoPE
    gemm_mma<<<gg, 256, G_SMEM>>>(x, wk, cache_k, fcos, fsin);   // fused RoPE
    gemm_mma<<<gg, 256, G_SMEM>>>(x, wv, cache_v, nullptr, nullptr);

    dim3 fg(SEQ / ABQ, NH, BSZ);      // (16, 32, 2)
    flash_mma<<<fg, 256, FA_SMEM>>>(qbuf, cache_k, cache_v, abuf);

    gemm_mma<<<gg, 256, G_SMEM>>>(abuf, wo, out, nullptr, nullptr);
}

// round 6
// speedup vs baseline: 4.0310x; 1.2443x over previous
#include <cuda_runtime.h>
#include <math.h>
#include <stdint.h>

#define DIM   4096
#define NH    32
#define HD    128
#define BSZ   2
#define SEQ   2048
#define NTOK  (BSZ*SEQ)          // 4096 tokens

// ---------------- scratch (allocation-free: __device__ globals) -------------
__device__ float g_q  [(size_t)NTOK * DIM];   // rotated Q (fp32)
__device__ float g_att[(size_t)NTOK * DIM];   // attention out (tf32-rounded bits)
__device__ float g_xt [(size_t)NTOK * DIM];   // tf32 x
__device__ float g_wqt[(size_t)DIM * DIM];    // tf32 weights
__device__ float g_wkt[(size_t)DIM * DIM];
__device__ float g_wvt[(size_t)DIM * DIM];
__device__ float g_wot[(size_t)DIM * DIM];

// ============================================================================
// helpers
// ============================================================================
__device__ __forceinline__ uint32_t smem_u32(const void* p) {
    uint32_t a;
    asm("{ .reg .u64 t; cvta.to.shared.u64 t, %1; cvt.u32.u64 %0, t; }"
        : "=r"(a) : "l"(p));
    return a;
}

__device__ __forceinline__ void cp16(uint32_t dst, const void* src) {
    asm volatile("cp.async.cg.shared.global [%0], [%1], 16;" :: "r"(dst), "l"(src));
}
#define CP_COMMIT() asm volatile("cp.async.commit_group;" ::: "memory")
#define CP_WAIT1()  asm volatile("cp.async.wait_group 1;"  ::: "memory")

__device__ __forceinline__ uint32_t f2tf(float f) {
    uint32_t r;
    asm("cvt.rna.tf32.f32 %0, %1;" : "=r"(r) : "f"(f));
    return r;
}
__device__ __forceinline__ float f2tf_f(float f) { return __uint_as_float(f2tf(f)); }

__device__ __forceinline__ void mma16n8k8(float* c, const uint32_t* a, const uint32_t* b) {
    asm volatile(
        "mma.sync.aligned.m16n8k8.row.col.f32.tf32.tf32.f32 "
        "{%0,%1,%2,%3}, {%4,%5,%6,%7}, {%8,%9}, {%0,%1,%2,%3};"
        : "+f"(c[0]), "+f"(c[1]), "+f"(c[2]), "+f"(c[3])
        : "r"(a[0]), "r"(a[1]), "r"(a[2]), "r"(a[3]), "r"(b[0]), "r"(b[1]));
}

// ============================================================================
// tf32 pre-rounding pass (rna) — removes all CVTs from GEMM mainloops
// ============================================================================
__global__ __launch_bounds__(256) void cvt_tf32(const float4* __restrict__ in,
                                                float4* __restrict__ out, int n4) {
    int i = blockIdx.x * blockDim.x + threadIdx.x;
    if (i < n4) {
        float4 v = in[i];
        v.x = f2tf_f(v.x); v.y = f2tf_f(v.y); v.z = f2tf_f(v.z); v.w = f2tf_f(v.w);
        out[i] = v;
    }
}

// ============================================================================
// tf32 mma.sync GEMM (NT), cvt-free: operands pre-rounded to tf32.
// C[m,n] = sum_k A[m,k]*B[n,k];  M=NTOK, N=K=4096
// CTA 256x128, 8 warps (4x2), warp tile 64x64, BK=32, 3-stage cp.async pipe.
// blockIdx.z selects (B, C, rope) — fused QKV in one launch.
// smem row stride 36 floats: fragment LDS patterns conflict-free.
// ============================================================================
#define GTM 256
#define GTN 128
#define GBK 32
#define GTS 36
#define GST 3
#define GNKI (DIM / GBK)                                   // 128
#define G_STAGE ((GTM + GTN) * GTS)                        // floats per stage
#define G_SMEM (GST * G_STAGE * 4)                         // 165888 B

__global__ __launch_bounds__(256, 1) void gemm_mma(
    const float* __restrict__ A,
    const float* __restrict__ B0, const float* __restrict__ B1, const float* __restrict__ B2,
    float* __restrict__ C0, float* __restrict__ C1, float* __restrict__ C2,
    const float* __restrict__ rcs, const float* __restrict__ rsn) {
    extern __shared__ float smf[];

    const int z = blockIdx.z;
    const float* B = (z == 0) ? B0 : ((z == 1) ? B1 : B2);
    float*       C = (z == 0) ? C0 : ((z == 1) ? C1 : C2);
    const bool do_rope = (rcs != nullptr) && (z < 2);

    const int t    = threadIdx.x;
    const int lane = t & 31;
    const int w    = t >> 5;
    const int wm   = w >> 1;          // 0..3
    const int wn   = w & 1;           // 0..1
    const int g    = lane >> 2;       // 0..7
    const int q    = lane & 3;        // 0..3
    const int bm   = blockIdx.y, bn = blockIdx.x;

    const uint32_t sS = smem_u32(smf);
    const int lr  = t >> 3;           // 0..31
    const int lc4 = (t & 7) * 4;      // 0,4,...,28
    const float* Agp = A + (size_t)(bm * GTM + lr) * DIM + lc4;
    const float* Bgp = B + (size_t)(bn * GTN + lr) * DIM + lc4;

    float acc[4][8][4];
#pragma unroll
    for (int i = 0; i < 4; i++)
#pragma unroll
        for (int j = 0; j < 8; j++)
#pragma unroll
            for (int v = 0; v < 4; v++) acc[i][j][v] = 0.f;

    // prologue: stages 0..GST-2
#pragma unroll
    for (int s = 0; s < GST - 1; s++) {
        const int k0 = s * GBK;
        const uint32_t dA = sS + s * (G_STAGE * 4);
        const uint32_t dB = dA + GTM * GTS * 4;
#pragma unroll
        for (int j = 0; j < 8; j++)
            cp16(dA + ((lr + j * 32) * GTS + lc4) * 4, Agp + (size_t)(j * 32) * DIM + k0);
#pragma unroll
        for (int j = 0; j < 4; j++)
            cp16(dB + ((lr + j * 32) * GTS + lc4) * 4, Bgp + (size_t)(j * 32) * DIM + k0);
        CP_COMMIT();
    }

    for (int i = 0; i < GNKI; i++) {
        CP_WAIT1();
        __syncthreads();

        if (i + GST - 1 < GNKI) {
            const int st = (i + GST - 1) % GST;
            const int k0 = (i + GST - 1) * GBK;
            const uint32_t dA = sS + st * (G_STAGE * 4);
            const uint32_t dB = dA + GTM * GTS * 4;
#pragma unroll
            for (int j = 0; j < 8; j++)
                cp16(dA + ((lr + j * 32) * GTS + lc4) * 4, Agp + (size_t)(j * 32) * DIM + k0);
#pragma unroll
            for (int j = 0; j < 4; j++)
                cp16(dB + ((lr + j * 32) * GTS + lc4) * 4, Bgp + (size_t)(j * 32) * DIM + k0);
        }
        CP_COMMIT();   // empty in tail: keeps group accounting valid

        const float* Ab = smf + (i % GST) * G_STAGE;
        const float* Bb = Ab + GTM * GTS;
#pragma unroll
        for (int k8 = 0; k8 < 4; k8++) {
            const int kc = k8 * 8 + q;
            uint32_t af[4][4], bf[8][2];
#pragma unroll
            for (int mt = 0; mt < 4; mt++) {
                const int r0 = wm * 64 + mt * 16 + g;
                af[mt][0] = __float_as_uint(Ab[r0 * GTS + kc]);
                af[mt][1] = __float_as_uint(Ab[(r0 + 8) * GTS + kc]);
                af[mt][2] = __float_as_uint(Ab[r0 * GTS + kc + 4]);
                af[mt][3] = __float_as_uint(Ab[(r0 + 8) * GTS + kc + 4]);
            }
#pragma unroll
            for (int nt = 0; nt < 8; nt++) {
                const int c0 = wn * 64 + nt * 8 + g;
                bf[nt][0] = __float_as_uint(Bb[c0 * GTS + kc]);
                bf[nt][1] = __float_as_uint(Bb[c0 * GTS + kc + 4]);
            }
#pragma unroll
            for (int mt = 0; mt < 4; mt++)
#pragma unroll
                for (int nt = 0; nt < 8; nt++)
                    mma16n8k8(acc[mt][nt], af[mt], bf[nt]);
        }
    }

    // epilogue (fused RoPE for Q/K: accumulator col pairs ARE rotary pairs)
#pragma unroll
    for (int mt = 0; mt < 4; mt++) {
        const size_t row = (size_t)bm * GTM + wm * 64 + mt * 16 + g;
#pragma unroll
        for (int nt = 0; nt < 8; nt++) {
            const int col = bn * GTN + wn * 64 + nt * 8 + q * 2;
            float2 v0 = {acc[mt][nt][0], acc[mt][nt][1]};
            float2 v1 = {acc[mt][nt][2], acc[mt][nt][3]};
            if (do_rope) {
                const int fi = (col & 127) >> 1;
                const int s0 = (int)(row & (SEQ - 1));
                const int s1 = (int)((row + 8) & (SEQ - 1));
                float c0 = rcs[s0 * 64 + fi], sn0 = rsn[s0 * 64 + fi];
                float c1 = rcs[s1 * 64 + fi], sn1 = rsn[s1 * 64 + fi];
                float2 r0 = {v0.x * c0 - v0.y * sn0, v0.x * sn0 + v0.y * c0};
                float2 r1 = {v1.x * c1 - v1.y * sn1, v1.x * sn1 + v1.y * c1};
                v0 = r0; v1 = r1;
            }
            *(float2*)(C + row * DIM + col)       = v0;
            *(float2*)(C + (row + 8) * DIM + col) = v1;
        }
    }
}

// ============================================================================
// Tensor-core flash attention (tf32 mma.sync): BQ=128, BK=64, 8 warps.
// K double-buffered + V single-buffered cp.async pipeline; in-place tf32
// convert of self-owned chunks. Output written tf32-rounded (feeds WO gemm).
// ============================================================================
#define ABQ 128
#define ABK 64
#define AQS 132
#define AKS 132
#define AVS 136
#define APS 68
#define FA_SMEM ((ABQ*AQS + 2*ABK*AKS + ABK*AVS + 8*16*APS) * 4)   // 204800 B

__global__ __launch_bounds__(256, 1) void flash_mma(const float* __restrict__ Q,
                                                    const float* __restrict__ Kc,
                                                    const float* __restrict__ Vc,
                                                    float* __restrict__ O) {
    extern __shared__ float sm[];
    float* Qs = sm;                              // 128 x 132
    float* Kb = Qs + ABQ * AQS;                  // 2 x (64 x 132)
    float* Vs = Kb + 2 * ABK * AKS;              // 64 x 136
    float* Ps = Vs + ABK * AVS;                  // 8 warps x 16 x 68

    const int t    = threadIdx.x;
    const int w    = t >> 5;
    const int lane = t & 31;
    const int g    = lane >> 2;
    const int q    = lane & 3;
    const int qt   = gridDim.x - 1 - blockIdx.x;   // longest tiles first
    const int h    = blockIdx.y, b = blockIdx.z;
    const float scale = 0.08838834764831845f;      // 1/sqrt(128)

    const uint32_t sKb = smem_u32(Kb);
    const uint32_t sVs = smem_u32(Vs);
    const int nkb = 2 * (qt + 1);

    auto issueK = [&](int kb, int buf) {
        const uint32_t base = sKb + (uint32_t)buf * (ABK * AKS * 4);
        for (int i = t; i < ABK * 32; i += 256) {
            int row = i >> 5, c4 = i & 31;
            size_t gk = ((size_t)((b * SEQ + kb * ABK + row) * NH + h)) * HD + c4 * 4;
            cp16(base + (row * AKS + c4 * 4) * 4, Kc + gk);
        }
    };
    auto issueV = [&](int kb) {
        for (int i = t; i < ABK * 32; i += 256) {
            int row = i >> 5, c4 = i & 31;
            size_t gk = ((size_t)((b * SEQ + kb * ABK + row) * NH + h)) * HD + c4 * 4;
            cp16(sVs + (row * AVS + c4 * 4) * 4, Vc + gk);
        }
    };

    issueK(0, 0); CP_COMMIT();
    issueV(0);    CP_COMMIT();
    for (int i = t; i < ABQ * 32; i += 256) {
        int row = i >> 5, c4 = i & 31;
        const float4 v = *(const float4*)(Q + ((size_t)((b * SEQ + qt * ABQ + row) * NH + h)) * HD + c4 * 4);
        float* d = Qs + row * AQS + c4 * 4;
        d[0] = f2tf_f(v.x); d[1] = f2tf_f(v.y); d[2] = f2tf_f(v.z); d[3] = f2tf_f(v.w);
    }

    float o[16][4];
#pragma unroll
    for (int i = 0; i < 16; i++)
#pragma unroll
        for (int v = 0; v < 4; v++) o[i][v] = 0.f;
    float mA = -INFINITY, mB = -INFINITY, lA = 0.f, lB = 0.f;

    float* Pw = Ps + w * 16 * APS;
    const int r0   = w * 16;
    const int rowA = qt * ABQ + r0 + g;            // rowB = rowA + 8
    __syncthreads();

    for (int kb = 0; kb < nkb; kb++) {
        if (kb + 1 < nkb) issueK(kb + 1, (kb + 1) & 1);
        CP_COMMIT();
        CP_WAIT1();          // K_kb and V_kb (own chunks) landed

        float* Kcur = Kb + (kb & 1) * (ABK * AKS);
        for (int i = t; i < ABK * 32; i += 256) {
            int row = i >> 5, c4 = i & 31;
            float4* pk = (float4*)(Kcur + row * AKS + c4 * 4);
            float4 kv = *pk;
            kv.x = f2tf_f(kv.x); kv.y = f2tf_f(kv.y); kv.z = f2tf_f(kv.z); kv.w = f2tf_f(kv.w);
            *pk = kv;
            float4* pv = (float4*)(Vs + row * AVS + c4 * 4);
            float4 vv = *pv;
            vv.x = f2tf_f(vv.x); vv.y = f2tf_f(vv.y); vv.z = f2tf_f(vv.z); vv.w = f2tf_f(vv.w);
            *pv = vv;
        }
        __syncthreads();

        const bool full_skip = (kb * ABK > qt * ABQ + r0 + 15);
        if (!full_skip) {
            float s[8][4];
#pragma unroll
            for (int i = 0; i < 8; i++)
#pragma unroll
                for (int v = 0; v < 4; v++) s[i][v] = 0.f;
#pragma unroll
            for (int k8 = 0; k8 < 16; k8++) {
                const int kc = k8 * 8 + q;
                uint32_t a[4];
                a[0] = __float_as_uint(Qs[(r0 + g) * AQS + kc]);
                a[1] = __float_as_uint(Qs[(r0 + g + 8) * AQS + kc]);
                a[2] = __float_as_uint(Qs[(r0 + g) * AQS + kc + 4]);
                a[3] = __float_as_uint(Qs[(r0 + g + 8) * AQS + kc + 4]);
#pragma unroll
                for (int nt = 0; nt < 8; nt++) {
                    uint32_t bfr[2];
                    bfr[0] = __float_as_uint(Kcur[(nt * 8 + g) * AKS + kc]);
                    bfr[1] = __float_as_uint(Kcur[(nt * 8 + g) * AKS + kc + 4]);
                    mma16n8k8(s[nt], a, bfr);
                }
            }
            const bool need_mask = (kb * ABK + ABK - 1 > qt * ABQ + r0);
#pragma unroll
            for (int nt = 0; nt < 8; nt++) {
                const int c0 = kb * ABK + nt * 8 + 2 * q;
                s[nt][0] *= scale; s[nt][1] *= scale;
                s[nt][2] *= scale; s[nt][3] *= scale;
                if (need_mask) {
                    if (c0     > rowA)     s[nt][0] = -1e30f;
                    if (c0 + 1 > rowA)     s[nt][1] = -1e30f;
                    if (c0     > rowA + 8) s[nt][2] = -1e30f;
                    if (c0 + 1 > rowA + 8) s[nt][3] = -1e30f;
                }
            }
            float mxA = -INFINITY, mxB = -INFINITY;
#pragma unroll
            for (int nt = 0; nt < 8; nt++) {
                mxA = fmaxf(mxA, fmaxf(s[nt][0], s[nt][1]));
                mxB = fmaxf(mxB, fmaxf(s[nt][2], s[nt][3]));
            }
            mxA = fmaxf(mxA, __shfl_xor_sync(0xffffffffu, mxA, 1));
            mxA = fmaxf(mxA, __shfl_xor_sync(0xffffffffu, mxA, 2));
            mxB = fmaxf(mxB, __shfl_xor_sync(0xffffffffu, mxB, 1));
            mxB = fmaxf(mxB, __shfl_xor_sync(0xffffffffu, mxB, 2));
            const float mnA = fmaxf(mA, mxA), mnB = fmaxf(mB, mxB);
            const float aA = __expf(mA - mnA), aB = __expf(mB - mnB);
            float sumA = 0.f, sumB = 0.f;
#pragma unroll
            for (int nt = 0; nt < 8; nt++) {
                float p0 = __expf(s[nt][0] - mnA), p1 = __expf(s[nt][1] - mnA);
                float p2 = __expf(s[nt][2] - mnB), p3 = __expf(s[nt][3] - mnB);
                sumA += p0 + p1; sumB += p2 + p3;
                float2 pa = {f2tf_f(p0), f2tf_f(p1)};
                float2 pb = {f2tf_f(p2), f2tf_f(p3)};
                *(float2*)(Pw + g * APS + nt * 8 + 2 * q)       = pa;
                *(float2*)(Pw + (g + 8) * APS + nt * 8 + 2 * q) = pb;
            }
            sumA += __shfl_xor_sync(0xffffffffu, sumA, 1);
            sumA += __shfl_xor_sync(0xffffffffu, sumA, 2);
            sumB += __shfl_xor_sync(0xffffffffu, sumB, 1);
            sumB += __shfl_xor_sync(0xffffffffu, sumB, 2);
            lA = lA * aA + sumA;  mA = mnA;
            lB = lB * aB + sumB;  mB = mnB;
#pragma unroll
            for (int nt = 0; nt < 16; nt++) {
                o[nt][0] *= aA; o[nt][1] *= aA;
                o[nt][2] *= aB; o[nt][3] *= aB;
            }
            __syncwarp();
#pragma unroll
            for (int k8 = 0; k8 < 8; k8++) {
                const int kc = k8 * 8 + q;
                uint32_t a[4];
                a[0] = __float_as_uint(Pw[g * APS + kc]);
                a[1] = __float_as_uint(Pw[(g + 8) * APS + kc]);
                a[2] = __float_as_uint(Pw[g * APS + kc + 4]);
                a[3] = __float_as_uint(Pw[(g + 8) * APS + kc + 4]);
#pragma unroll
                for (int nt = 0; nt < 16; nt++) {
                    uint32_t bfr[2];
                    bfr[0] = __float_as_uint(Vs[kc * AVS + nt * 8 + g]);
                    bfr[1] = __float_as_uint(Vs[(kc + 4) * AVS + nt * 8 + g]);
                    mma16n8k8(o[nt], a, bfr);
                }
            }
        }
        __syncthreads();     // everyone done with Vs before refill

        if (kb + 1 < nkb) issueV(kb + 1);
        CP_COMMIT();
    }

    // write tf32-rounded (identical arithmetic: WO mma rounds anyway)
    const float invA = 1.f / lA, invB = 1.f / lB;
    const size_t baseA = ((size_t)((b * SEQ + rowA) * NH + h)) * HD;
    const size_t baseB = baseA + (size_t)8 * NH * HD;
#pragma unroll
    for (int nt = 0; nt < 16; nt++) {
        float2 va = {f2tf_f(o[nt][0] * invA), f2tf_f(o[nt][1] * invA)};
        float2 vb = {f2tf_f(o[nt][2] * invB), f2tf_f(o[nt][3] * invB)};
        *(float2*)(O + baseA + nt * 8 + 2 * q) = va;
        *(float2*)(O + baseB + nt * 8 + 2 * q) = vb;
    }
}

// ============================================================================
// launch
// ============================================================================
extern "C" void kernel_launch(void* const* d_in, const int* in_sizes, int n_in,
                              void* d_out, int out_size) {
    const float* x    = (const float*)d_in[0];
    const float* fcos = (const float*)d_in[1];
    const float* fsin = (const float*)d_in[2];
    // d_in[3] mask, d_in[4] input_idexes, d_in[5] cache_k, d_in[6] cache_v: unused
    const float* wq = (const float*)d_in[7];
    const float* wk = (const float*)d_in[8];
    const float* wv = (const float*)d_in[9];
    const float* wo = (const float*)d_in[10];

    float* out     = (float*)d_out;                               // [B,S,DIM]
    float* cache_k = (float*)d_out + (size_t)NTOK * DIM;          // [B,S,NH,HD]
    float* cache_v = (float*)d_out + (size_t)2 * NTOK * DIM;      // [B,S,NH,HD]

    float* qbuf; cudaGetSymbolAddress((void**)&qbuf, g_q);
    float* abuf; cudaGetSymbolAddress((void**)&abuf, g_att);
    float* xt;   cudaGetSymbolAddress((void**)&xt,   g_xt);
    float* wqt;  cudaGetSymbolAddress((void**)&wqt,  g_wqt);
    float* wkt;  cudaGetSymbolAddress((void**)&wkt,  g_wkt);
    float* wvt;  cudaGetSymbolAddress((void**)&wvt,  g_wvt);
    float* wot;  cudaGetSymbolAddress((void**)&wot,  g_wot);

    cudaFuncSetAttribute(gemm_mma,  cudaFuncAttributeMaxDynamicSharedMemorySize, G_SMEM);
    cudaFuncSetAttribute(flash_mma, cudaFuncAttributeMaxDynamicSharedMemorySize, FA_SMEM);

    const int N4 = NTOK * DIM / 4;         // 4M float4 per 64MB buffer
    const int cb = (N4 + 255) / 256;
    cvt_tf32<<<cb, 256>>>((const float4*)x,  (float4*)xt,  N4);
    cvt_tf32<<<cb, 256>>>((const float4*)wq, (float4*)wqt, N4);
    cvt_tf32<<<cb, 256>>>((const float4*)wk, (float4*)wkt, N4);
    cvt_tf32<<<cb, 256>>>((const float4*)wv, (float4*)wvt, N4);
    cvt_tf32<<<cb, 256>>>((const float4*)wo, (float4*)wot, N4);

    // fused QKV: z=0 -> Q (rope), z=1 -> K (rope), z=2 -> V
    dim3 gq(DIM / GTN, NTOK / GTM, 3);     // (32, 16, 3)
    gemm_mma<<<gq, 256, G_SMEM>>>(xt, wqt, wkt, wvt, qbuf, cache_k, cache_v, fcos, fsin);

    dim3 fg(SEQ / ABQ, NH, BSZ);           // (16, 32, 2)
    flash_mma<<<fg, 256, FA_SMEM>>>(qbuf, cache_k, cache_v, abuf);

    dim3 gw(DIM / GTN, NTOK / GTM, 1);     // (32, 16)
    gemm_mma<<<gw, 256, G_SMEM>>>(abuf, wot, wot, wot, out, out, out, nullptr, nullptr);
}

// round 7
// speedup vs baseline: 4.2939x; 1.0652x over previous
#include <cuda_runtime.h>
#include <math.h>
#include <stdint.h>

#define DIM   4096
#define NH    32
#define HD    128
#define BSZ   2
#define SEQ   2048
#define NTOK  (BSZ*SEQ)          // 4096 tokens

// ---------------- scratch (allocation-free: __device__ globals) -------------
__device__ float g_q  [(size_t)NTOK * DIM];   // rotated Q (fp32/tf32 bits)
__device__ float g_att[(size_t)NTOK * DIM];   // attention out (tf32 bits)
__device__ float g_xt [(size_t)NTOK * DIM];   // tf32+perm x / reused for abuf-perm
__device__ float g_wqt[(size_t)DIM * DIM];    // tf32+perm weights
__device__ float g_wkt[(size_t)DIM * DIM];
__device__ float g_wvt[(size_t)DIM * DIM];
__device__ float g_wot[(size_t)DIM * DIM];

// ============================================================================
// helpers
// ============================================================================
__device__ __forceinline__ uint32_t smem_u32(const void* p) {
    uint32_t a;
    asm("{ .reg .u64 t; cvta.to.shared.u64 t, %1; cvt.u32.u64 %0, t; }"
        : "=r"(a) : "l"(p));
    return a;
}

__device__ __forceinline__ void cp16(uint32_t dst, const void* src) {
    asm volatile("cp.async.cg.shared.global [%0], [%1], 16;" :: "r"(dst), "l"(src));
}
#define CP_COMMIT() asm volatile("cp.async.commit_group;" ::: "memory")
#define CP_WAIT1()  asm volatile("cp.async.wait_group 1;"  ::: "memory")

__device__ __forceinline__ uint32_t f2tf(float f) {
    uint32_t r;
    asm("cvt.rna.tf32.f32 %0, %1;" : "=r"(r) : "f"(f));
    return r;
}
__device__ __forceinline__ float f2tf_f(float f) { return __uint_as_float(f2tf(f)); }

__device__ __forceinline__ void mma16n8k8(float* c, const uint32_t* a, const uint32_t* b) {
    asm volatile(
        "mma.sync.aligned.m16n8k8.row.col.f32.tf32.tf32.f32 "
        "{%0,%1,%2,%3}, {%4,%5,%6,%7}, {%8,%9}, {%0,%1,%2,%3};"
        : "+f"(c[0]), "+f"(c[1]), "+f"(c[2]), "+f"(c[3])
        : "r"(a[0]), "r"(a[1]), "r"(a[2]), "r"(a[3]), "r"(b[0]), "r"(b[1]));
}

// ============================================================================
// tf32 rounding + k-group permutation pass.
// Each 8-float k-group [a0..a7] is stored as [a0,a4,a1,a5,a2,a6,a3,a7] so that
// the (kc, kc+4) mma fragment pair becomes one aligned float2 in smem.
// ============================================================================
__global__ __launch_bounds__(256) void cvt_perm(const float4* __restrict__ in,
                                                float4* __restrict__ out, int n8) {
    int i = blockIdx.x * blockDim.x + threadIdx.x;
    if (i < n8) {
        float4 a = in[2 * i], b = in[2 * i + 1];
        float4 o0 = {f2tf_f(a.x), f2tf_f(b.x), f2tf_f(a.y), f2tf_f(b.y)};
        float4 o1 = {f2tf_f(a.z), f2tf_f(b.z), f2tf_f(a.w), f2tf_f(b.w)};
        out[2 * i]     = o0;
        out[2 * i + 1] = o1;
    }
}

// ============================================================================
// tf32 mma.sync GEMM (NT), cvt-free, float2 fragment loads (permuted K).
// C[m,n] = sum_k A[m,k]*B[n,k];  M=NTOK, N=K=4096
// CTA 256x128, 8 warps (4x2), warp tile 64x64, BK=32, 3-stage cp.async pipe.
// smem row stride 40 floats: LDS.64 conflict-free per 16-lane phase.
// blockIdx.z selects (B, C, rope) — fused QKV in one launch.
// ============================================================================
#define GTM 256
#define GTN 128
#define GBK 32
#define GTS 40
#define GST 3
#define GNKI (DIM / GBK)                                   // 128
#define G_STAGE ((GTM + GTN) * GTS)                        // floats per stage
#define G_SMEM (GST * G_STAGE * 4)                         // 184320 B

__global__ __launch_bounds__(256, 1) void gemm_mma(
    const float* __restrict__ A,
    const float* __restrict__ B0, const float* __restrict__ B1, const float* __restrict__ B2,
    float* __restrict__ C0, float* __restrict__ C1, float* __restrict__ C2,
    const float* __restrict__ rcs, const float* __restrict__ rsn) {
    extern __shared__ float smf[];

    const int z = blockIdx.z;
    const float* B = (z == 0) ? B0 : ((z == 1) ? B1 : B2);
    float*       C = (z == 0) ? C0 : ((z == 1) ? C1 : C2);
    const bool do_rope = (rcs != nullptr) && (z < 2);

    const int t    = threadIdx.x;
    const int lane = t & 31;
    const int w    = t >> 5;
    const int wm   = w >> 1;          // 0..3
    const int wn   = w & 1;           // 0..1
    const int g    = lane >> 2;       // 0..7
    const int q    = lane & 3;        // 0..3
    const int bm   = blockIdx.y, bn = blockIdx.x;

    const uint32_t sS = smem_u32(smf);
    const int lr  = t >> 3;           // 0..31
    const int lc4 = (t & 7) * 4;      // 0,4,...,28
    const float* Agp = A + (size_t)(bm * GTM + lr) * DIM + lc4;
    const float* Bgp = B + (size_t)(bn * GTN + lr) * DIM + lc4;

    float acc[4][8][4];
#pragma unroll
    for (int i = 0; i < 4; i++)
#pragma unroll
        for (int j = 0; j < 8; j++)
#pragma unroll
            for (int v = 0; v < 4; v++) acc[i][j][v] = 0.f;

    // prologue: stages 0..GST-2
#pragma unroll
    for (int s = 0; s < GST - 1; s++) {
        const int k0 = s * GBK;
        const uint32_t dA = sS + s * (G_STAGE * 4);
        const uint32_t dB = dA + GTM * GTS * 4;
#pragma unroll
        for (int j = 0; j < 8; j++)
            cp16(dA + ((lr + j * 32) * GTS + lc4) * 4, Agp + (size_t)(j * 32) * DIM + k0);
#pragma unroll
        for (int j = 0; j < 4; j++)
            cp16(dB + ((lr + j * 32) * GTS + lc4) * 4, Bgp + (size_t)(j * 32) * DIM + k0);
        CP_COMMIT();
    }

    for (int i = 0; i < GNKI; i++) {
        CP_WAIT1();
        __syncthreads();

        if (i + GST - 1 < GNKI) {
            const int st = (i + GST - 1) % GST;
            const int k0 = (i + GST - 1) * GBK;
            const uint32_t dA = sS + st * (G_STAGE * 4);
            const uint32_t dB = dA + GTM * GTS * 4;
#pragma unroll
            for (int j = 0; j < 8; j++)
                cp16(dA + ((lr + j * 32) * GTS + lc4) * 4, Agp + (size_t)(j * 32) * DIM + k0);
#pragma unroll
            for (int j = 0; j < 4; j++)
                cp16(dB + ((lr + j * 32) * GTS + lc4) * 4, Bgp + (size_t)(j * 32) * DIM + k0);
        }
        CP_COMMIT();   // empty in tail: keeps group accounting valid

        const float* Ab = smf + (i % GST) * G_STAGE;
        const float* Bb = Ab + GTM * GTS;
#pragma unroll
        for (int k8 = 0; k8 < 4; k8++) {
            const int ks = k8 * 8 + 2 * q;        // permuted slot of (kc, kc+4)
            uint32_t af[4][4], bf[8][2];
#pragma unroll
            for (int mt = 0; mt < 4; mt++) {
                const int r0 = wm * 64 + mt * 16 + g;
                float2 u0 = *(const float2*)(Ab + r0 * GTS + ks);
                float2 u1 = *(const float2*)(Ab + (r0 + 8) * GTS + ks);
                af[mt][0] = __float_as_uint(u0.x);
                af[mt][1] = __float_as_uint(u1.x);
                af[mt][2] = __float_as_uint(u0.y);
                af[mt][3] = __float_as_uint(u1.y);
            }
#pragma unroll
            for (int nt = 0; nt < 8; nt++) {
                const int c0 = wn * 64 + nt * 8 + g;
                float2 v = *(const float2*)(Bb + c0 * GTS + ks);
                bf[nt][0] = __float_as_uint(v.x);
                bf[nt][1] = __float_as_uint(v.y);
            }
#pragma unroll
            for (int mt = 0; mt < 4; mt++)
#pragma unroll
                for (int nt = 0; nt < 8; nt++)
                    mma16n8k8(acc[mt][nt], af[mt], bf[nt]);
        }
    }

    // epilogue (fused RoPE for Q/K: accumulator col pairs ARE rotary pairs)
#pragma unroll
    for (int mt = 0; mt < 4; mt++) {
        const size_t row = (size_t)bm * GTM + wm * 64 + mt * 16 + g;
#pragma unroll
        for (int nt = 0; nt < 8; nt++) {
            const int col = bn * GTN + wn * 64 + nt * 8 + q * 2;
            float2 v0 = {acc[mt][nt][0], acc[mt][nt][1]};
            float2 v1 = {acc[mt][nt][2], acc[mt][nt][3]};
            if (do_rope) {
                const int fi = (col & 127) >> 1;
                const int s0 = (int)(row & (SEQ - 1));
                const int s1 = (int)((row + 8) & (SEQ - 1));
                float c0 = rcs[s0 * 64 + fi], sn0 = rsn[s0 * 64 + fi];
                float c1 = rcs[s1 * 64 + fi], sn1 = rsn[s1 * 64 + fi];
                float2 r0 = {v0.x * c0 - v0.y * sn0, v0.x * sn0 + v0.y * c0};
                float2 r1 = {v1.x * c1 - v1.y * sn1, v1.x * sn1 + v1.y * c1};
                v0 = r0; v1 = r1;
            }
            *(float2*)(C + row * DIM + col)       = v0;
            *(float2*)(C + (row + 8) * DIM + col) = v1;
        }
    }
}

// ============================================================================
// Tensor-core flash attention (tf32 mma.sync): BQ=128, BK=64, 8 warps.
// K double-buffered + V single-buffered cp.async pipeline; in-place tf32
// convert of self-owned chunks. Output written tf32-rounded (feeds WO gemm).
// ============================================================================
#define ABQ 128
#define ABK 64
#define AQS 132
#define AKS 132
#define AVS 136
#define APS 68
#define FA_SMEM ((ABQ*AQS + 2*ABK*AKS + ABK*AVS + 8*16*APS) * 4)   // 204800 B

__global__ __launch_bounds__(256, 1) void flash_mma(const float* __restrict__ Q,
                                                    const float* __restrict__ Kc,
                                                    const float* __restrict__ Vc,
                                                    float* __restrict__ O) {
    extern __shared__ float sm[];
    float* Qs = sm;                              // 128 x 132
    float* Kb = Qs + ABQ * AQS;                  // 2 x (64 x 132)
    float* Vs = Kb + 2 * ABK * AKS;              // 64 x 136
    float* Ps = Vs + ABK * AVS;                  // 8 warps x 16 x 68

    const int t    = threadIdx.x;
    const int w    = t >> 5;
    const int lane = t & 31;
    const int g    = lane >> 2;
    const int q    = lane & 3;
    const int qt   = gridDim.x - 1 - blockIdx.x;   // longest tiles first
    const int h    = blockIdx.y, b = blockIdx.z;
    const float scale = 0.08838834764831845f;      // 1/sqrt(128)

    const uint32_t sKb = smem_u32(Kb);
    const uint32_t sVs = smem_u32(Vs);
    const int nkb = 2 * (qt + 1);

    auto issueK = [&](int kb, int buf) {
        const uint32_t base = sKb + (uint32_t)buf * (ABK * AKS * 4);
        for (int i = t; i < ABK * 32; i += 256) {
            int row = i >> 5, c4 = i & 31;
            size_t gk = ((size_t)((b * SEQ + kb * ABK + row) * NH + h)) * HD + c4 * 4;
            cp16(base + (row * AKS + c4 * 4) * 4, Kc + gk);
        }
    };
    auto issueV = [&](int kb) {
        for (int i = t; i < ABK * 32; i += 256) {
            int row = i >> 5, c4 = i & 31;
            size_t gk = ((size_t)((b * SEQ + kb * ABK + row) * NH + h)) * HD + c4 * 4;
            cp16(sVs + (row * AVS + c4 * 4) * 4, Vc + gk);
        }
    };

    issueK(0, 0); CP_COMMIT();
    issueV(0);    CP_COMMIT();
    for (int i = t; i < ABQ * 32; i += 256) {
        int row = i >> 5, c4 = i & 31;
        const float4 v = *(const float4*)(Q + ((size_t)((b * SEQ + qt * ABQ + row) * NH + h)) * HD + c4 * 4);
        float* d = Qs + row * AQS + c4 * 4;
        d[0] = f2tf_f(v.x); d[1] = f2tf_f(v.y); d[2] = f2tf_f(v.z); d[3] = f2tf_f(v.w);
    }

    float o[16][4];
#pragma unroll
    for (int i = 0; i < 16; i++)
#pragma unroll
        for (int v = 0; v < 4; v++) o[i][v] = 0.f;
    float mA = -INFINITY, mB = -INFINITY, lA = 0.f, lB = 0.f;

    float* Pw = Ps + w * 16 * APS;
    const int r0   = w * 16;
    const int rowA = qt * ABQ + r0 + g;            // rowB = rowA + 8
    __syncthreads();

    for (int kb = 0; kb < nkb; kb++) {
        if (kb + 1 < nkb) issueK(kb + 1, (kb + 1) & 1);
        CP_COMMIT();
        CP_WAIT1();          // K_kb and V_kb (own chunks) landed

        float* Kcur = Kb + (kb & 1) * (ABK * AKS);
        for (int i = t; i < ABK * 32; i += 256) {
            int row = i >> 5, c4 = i & 31;
            float4* pk = (float4*)(Kcur + row * AKS + c4 * 4);
            float4 kv = *pk;
            kv.x = f2tf_f(kv.x); kv.y = f2tf_f(kv.y); kv.z = f2tf_f(kv.z); kv.w = f2tf_f(kv.w);
            *pk = kv;
            float4* pv = (float4*)(Vs + row * AVS + c4 * 4);
            float4 vv = *pv;
            vv.x = f2tf_f(vv.x); vv.y = f2tf_f(vv.y); vv.z = f2tf_f(vv.z); vv.w = f2tf_f(vv.w);
            *pv = vv;
        }
        __syncthreads();

        const bool full_skip = (kb * ABK > qt * ABQ + r0 + 15);
        if (!full_skip) {
            float s[8][4];
#pragma unroll
            for (int i = 0; i < 8; i++)
#pragma unroll
                for (int v = 0; v < 4; v++) s[i][v] = 0.f;
#pragma unroll
            for (int k8 = 0; k8 < 16; k8++) {
                const int kc = k8 * 8 + q;
                uint32_t a[4];
                a[0] = __float_as_uint(Qs[(r0 + g) * AQS + kc]);
                a[1] = __float_as_uint(Qs[(r0 + g + 8) * AQS + kc]);
                a[2] = __float_as_uint(Qs[(r0 + g) * AQS + kc + 4]);
                a[3] = __float_as_uint(Qs[(r0 + g + 8) * AQS + kc + 4]);
#pragma unroll
                for (int nt = 0; nt < 8; nt++) {
                    uint32_t bfr[2];
                    bfr[0] = __float_as_uint(Kcur[(nt * 8 + g) * AKS + kc]);
                    bfr[1] = __float_as_uint(Kcur[(nt * 8 + g) * AKS + kc + 4]);
                    mma16n8k8(s[nt], a, bfr);
                }
            }
            const bool need_mask = (kb * ABK + ABK - 1 > qt * ABQ + r0);
#pragma unroll
            for (int nt = 0; nt < 8; nt++) {
                const int c0 = kb * ABK + nt * 8 + 2 * q;
                s[nt][0] *= scale; s[nt][1] *= scale;
                s[nt][2] *= scale; s[nt][3] *= scale;
                if (need_mask) {
                    if (c0     > rowA)     s[nt][0] = -1e30f;
                    if (c0 + 1 > rowA)     s[nt][1] = -1e30f;
                    if (c0     > rowA + 8) s[nt][2] = -1e30f;
                    if (c0 + 1 > rowA + 8) s[nt][3] = -1e30f;
                }
            }
            float mxA = -INFINITY, mxB = -INFINITY;
#pragma unroll
            for (int nt = 0; nt < 8; nt++) {
                mxA = fmaxf(mxA, fmaxf(s[nt][0], s[nt][1]));
                mxB = fmaxf(mxB, fmaxf(s[nt][2], s[nt][3]));
            }
            mxA = fmaxf(mxA, __shfl_xor_sync(0xffffffffu, mxA, 1));
            mxA = fmaxf(mxA, __shfl_xor_sync(0xffffffffu, mxA, 2));
            mxB = fmaxf(mxB, __shfl_xor_sync(0xffffffffu, mxB, 1));
            mxB = fmaxf(mxB, __shfl_xor_sync(0xffffffffu, mxB, 2));
            const float mnA = fmaxf(mA, mxA), mnB = fmaxf(mB, mxB);
            const float aA = __expf(mA - mnA), aB = __expf(mB - mnB);
            float sumA = 0.f, sumB = 0.f;
#pragma unroll
            for (int nt = 0; nt < 8; nt++) {
                float p0 = __expf(s[nt][0] - mnA), p1 = __expf(s[nt][1] - mnA);
                float p2 = __expf(s[nt][2] - mnB), p3 = __expf(s[nt][3] - mnB);
                sumA += p0 + p1; sumB += p2 + p3;
                float2 pa = {f2tf_f(p0), f2tf_f(p1)};
                float2 pb = {f2tf_f(p2), f2tf_f(p3)};
                *(float2*)(Pw + g * APS + nt * 8 + 2 * q)       = pa;
                *(float2*)(Pw + (g + 8) * APS + nt * 8 + 2 * q) = pb;
            }
            sumA += __shfl_xor_sync(0xffffffffu, sumA, 1);
            sumA += __shfl_xor_sync(0xffffffffu, sumA, 2);
            sumB += __shfl_xor_sync(0xffffffffu, sumB, 1);
            sumB += __shfl_xor_sync(0xffffffffu, sumB, 2);
            lA = lA * aA + sumA;  mA = mnA;
            lB = lB * aB + sumB;  mB = mnB;
#pragma unroll
            for (int nt = 0; nt < 16; nt++) {
                o[nt][0] *= aA; o[nt][1] *= aA;
                o[nt][2] *= aB; o[nt][3] *= aB;
            }
            __syncwarp();
#pragma unroll
            for (int k8 = 0; k8 < 8; k8++) {
                const int kc = k8 * 8 + q;
                uint32_t a[4];
                a[0] = __float_as_uint(Pw[g * APS + kc]);
                a[1] = __float_as_uint(Pw[(g + 8) * APS + kc]);
                a[2] = __float_as_uint(Pw[g * APS + kc + 4]);
                a[3] = __float_as_uint(Pw[(g + 8) * APS + kc + 4]);
#pragma unroll
                for (int nt = 0; nt < 16; nt++) {
                    uint32_t bfr[2];
                    bfr[0] = __float_as_uint(Vs[kc * AVS + nt * 8 + g]);
                    bfr[1] = __float_as_uint(Vs[(kc + 4) * AVS + nt * 8 + g]);
                    mma16n8k8(o[nt], a, bfr);
                }
            }
        }
        __syncthreads();     // everyone done with Vs before refill

        if (kb + 1 < nkb) issueV(kb + 1);
        CP_COMMIT();
    }

    // write tf32-rounded (identical arithmetic: WO mma rounds anyway)
    const float invA = 1.f / lA, invB = 1.f / lB;
    const size_t baseA = ((size_t)((b * SEQ + rowA) * NH + h)) * HD;
    const size_t baseB = baseA + (size_t)8 * NH * HD;
#pragma unroll
    for (int nt = 0; nt < 16; nt++) {
        float2 va = {f2tf_f(o[nt][0] * invA), f2tf_f(o[nt][1] * invA)};
        float2 vb = {f2tf_f(o[nt][2] * invB), f2tf_f(o[nt][3] * invB)};
        *(float2*)(O + baseA + nt * 8 + 2 * q) = va;
        *(float2*)(O + baseB + nt * 8 + 2 * q) = vb;
    }
}

// ============================================================================
// launch
// ============================================================================
extern "C" void kernel_launch(void* const* d_in, const int* in_sizes, int n_in,
                              void* d_out, int out_size) {
    const float* x    = (const float*)d_in[0];
    const float* fcos = (const float*)d_in[1];
    const float* fsin = (const float*)d_in[2];
    // d_in[3] mask, d_in[4] input_idexes, d_in[5] cache_k, d_in[6] cache_v: unused
    const float* wq = (const float*)d_in[7];
    const float* wk = (const float*)d_in[8];
    const float* wv = (const float*)d_in[9];
    const float* wo = (const float*)d_in[10];

    float* out     = (float*)d_out;                               // [B,S,DIM]
    float* cache_k = (float*)d_out + (size_t)NTOK * DIM;          // [B,S,NH,HD]
    float* cache_v = (float*)d_out + (size_t)2 * NTOK * DIM;      // [B,S,NH,HD]

    float* qbuf; cudaGetSymbolAddress((void**)&qbuf, g_q);
    float* abuf; cudaGetSymbolAddress((void**)&abuf, g_att);
    float* xt;   cudaGetSymbolAddress((void**)&xt,   g_xt);
    float* wqt;  cudaGetSymbolAddress((void**)&wqt,  g_wqt);
    float* wkt;  cudaGetSymbolAddress((void**)&wkt,  g_wkt);
    float* wvt;  cudaGetSymbolAddress((void**)&wvt,  g_wvt);
    float* wot;  cudaGetSymbolAddress((void**)&wot,  g_wot);

    cudaFuncSetAttribute(gemm_mma,  cudaFuncAttributeMaxDynamicSharedMemorySize, G_SMEM);
    cudaFuncSetAttribute(flash_mma, cudaFuncAttributeMaxDynamicSharedMemorySize, FA_SMEM);

    const int N8 = NTOK * DIM / 8;         // 8-float groups per 64MB buffer
    const int cb = (N8 + 255) / 256;
    cvt_perm<<<cb, 256>>>((const float4*)x,  (float4*)xt,  N8);
    cvt_perm<<<cb, 256>>>((const float4*)wq, (float4*)wqt, N8);
    cvt_perm<<<cb, 256>>>((const float4*)wk, (float4*)wkt, N8);
    cvt_perm<<<cb, 256>>>((const float4*)wv, (float4*)wvt, N8);
    cvt_perm<<<cb, 256>>>((const float4*)wo, (float4*)wot, N8);

    // fused QKV: z=0 -> Q (rope), z=1 -> K (rope), z=2 -> V
    dim3 gq(DIM / GTN, NTOK / GTM, 3);     // (32, 16, 3)
    gemm_mma<<<gq, 256, G_SMEM>>>(xt, wqt, wkt, wvt, qbuf, cache_k, cache_v, fcos, fsin);

    dim3 fg(SEQ / ABQ, NH, BSZ);           // (16, 32, 2)
    flash_mma<<<fg, 256, FA_SMEM>>>(qbuf, cache_k, cache_v, abuf);

    // permute attention output's K-dim (rounding idempotent), then WO gemm
    cvt_perm<<<cb, 256>>>((const float4*)abuf, (float4*)xt, N8);
    dim3 gw(DIM / GTN, NTOK / GTM, 1);     // (32, 16)
    gemm_mma<<<gw, 256, G_SMEM>>>(xt, wot, wot, wot, out, out, out, nullptr, nullptr);
}